// round 1
// baseline (speedup 1.0000x reference)
#include <cuda_runtime.h>
#include <math.h>

#define MODEL_DIM 2048
#define INNER_DIM 512
#define NUM_HEADS 16
#define FFN_DIM   8192
#define MEM_TOKENS 64
#define BATCH 2
#define SEQ   2048
#define NTOK  (BATCH*SEQ)            // 4096
#define DH    (MODEL_DIM/NUM_HEADS)  // 128
#define EPSV  1e-6f

#define NCHUNK 32
#define CS     (SEQ/NCHUNK)          // 64
#define NBH    (BATCH*NUM_HEADS)     // 32

// ---------------- scratch (static device globals; no allocation) ------------
__device__ float g_xn   [NTOK*MODEL_DIM];
__device__ float g_k    [NTOK*MODEL_DIM];
__device__ float g_z    [NTOK*MODEL_DIM];
__device__ float g_glin [NTOK*MODEL_DIM];
__device__ float g_u    [NTOK*INNER_DIM];
__device__ float g_t    [NTOK*MODEL_DIM];
__device__ float g_m2   [NTOK*MODEL_DIM];
__device__ float g_gamma[NTOK*MODEL_DIM];
__device__ float g_ht   [NTOK*MODEL_DIM];
__device__ float g_qa   [NTOK*MODEL_DIM];
__device__ float g_ka   [BATCH*MEM_TOKENS*MODEL_DIM];
__device__ float g_va   [BATCH*MEM_TOKENS*MODEL_DIM];
__device__ float g_ctx  [NTOK*MODEL_DIM];
__device__ float g_xres [NTOK*MODEL_DIM];
__device__ float g_xn2  [NTOK*MODEL_DIM];
__device__ float g_a1   [NTOK*FFN_DIM];
__device__ float g_cp_tot [NBH*NCHUNK*DH];
__device__ float g_cp_pref[NBH*NCHUNK*DH];

// ---------------- helpers ---------------------------------------------------
__device__ __forceinline__ float gelu_f(float v) {
    // jax.nn.gelu default (approximate=True, tanh)
    float t = 0.7978845608028654f * (v + 0.044715f * v * v * v);
    return 0.5f * v * (1.0f + tanhf(t));
}
__device__ __forceinline__ float sigmoid_f(float v) {
    return 1.0f / (1.0f + expf(-v));
}

// ---------------- RMSNorm ----------------------------------------------------
// norm = sqrt(sum(x^2)/D); out = w * x / (norm + eps)
__global__ void rmsnorm_kernel(const float* __restrict__ x,
                               const float* __restrict__ w,
                               float* __restrict__ out) {
    int row = blockIdx.x;
    int t = threadIdx.x; // 256
    const float4* xr = (const float4*)(x + (long)row * MODEL_DIM);
    float4 v0 = xr[t];
    float4 v1 = xr[t + 256];
    float s = v0.x*v0.x + v0.y*v0.y + v0.z*v0.z + v0.w*v0.w
            + v1.x*v1.x + v1.y*v1.y + v1.z*v1.z + v1.w*v1.w;
    #pragma unroll
    for (int o = 16; o > 0; o >>= 1) s += __shfl_xor_sync(0xffffffffu, s, o);
    __shared__ float red[8];
    if ((t & 31) == 0) red[t >> 5] = s;
    __syncthreads();
    float tot = red[0]+red[1]+red[2]+red[3]+red[4]+red[5]+red[6]+red[7];
    float inv = 1.0f / (sqrtf(tot / (float)MODEL_DIM) + EPSV);
    const float4* wr = (const float4*)w;
    float4 w0 = wr[t], w1 = wr[t + 256];
    float4 o0, o1;
    o0.x = w0.x*v0.x*inv; o0.y = w0.y*v0.y*inv; o0.z = w0.z*v0.z*inv; o0.w = w0.w*v0.w*inv;
    o1.x = w1.x*v1.x*inv; o1.y = w1.y*v1.y*inv; o1.z = w1.z*v1.z*inv; o1.w = w1.w*v1.w*inv;
    float4* orow = (float4*)(out + (long)row * MODEL_DIM);
    orow[t] = o0; orow[t + 256] = o1;
}

// ---------------- generic SGEMM: C = A[N,K] @ W[K,Dout] + bias (+epi) --------
// EPI: 0 = none, 1 = gelu, 2 = +add1+add2, 3 = +add1
template <int EPI>
__global__ void gemm_kernel(const float* __restrict__ A,
                            const float* __restrict__ W,
                            const float* __restrict__ bias,
                            float* __restrict__ C,
                            int N, int K, int Dout,
                            const float* __restrict__ add1,
                            const float* __restrict__ add2) {
    constexpr int BM = 128, BN = 128, BK = 16;
    __shared__ float As[BK][BM];
    __shared__ float Bs[BK][BN];
    int tid = threadIdx.x;              // 256
    int bn = blockIdx.x, bm = blockIdx.y;
    int tx = tid & 15, ty = tid >> 4;   // 16x16 threads, each 8x8
    float acc[8][8];
    #pragma unroll
    for (int i = 0; i < 8; i++)
        #pragma unroll
        for (int j = 0; j < 8; j++) acc[i][j] = 0.0f;

    const float* Ab = A + (long)bm * BM * K;
    const float* Wb = W + bn * BN;
    int a_row  = tid >> 2;          // 0..63 (and +64)
    int a_col  = (tid & 3) * 4;     // 0,4,8,12
    int w_row  = tid >> 5;          // 0..7 (and +8)
    int w_col  = (tid & 31) * 4;    // 0..124

    for (int k0 = 0; k0 < K; k0 += BK) {
        float4 av0 = *(const float4*)(Ab + (long)a_row        * K + k0 + a_col);
        float4 av1 = *(const float4*)(Ab + (long)(a_row + 64) * K + k0 + a_col);
        As[a_col + 0][a_row] = av0.x; As[a_col + 1][a_row] = av0.y;
        As[a_col + 2][a_row] = av0.z; As[a_col + 3][a_row] = av0.w;
        As[a_col + 0][a_row + 64] = av1.x; As[a_col + 1][a_row + 64] = av1.y;
        As[a_col + 2][a_row + 64] = av1.z; As[a_col + 3][a_row + 64] = av1.w;
        float4 wv0 = *(const float4*)(Wb + (long)(k0 + w_row)     * Dout + w_col);
        float4 wv1 = *(const float4*)(Wb + (long)(k0 + w_row + 8) * Dout + w_col);
        *(float4*)&Bs[w_row][w_col]     = wv0;
        *(float4*)&Bs[w_row + 8][w_col] = wv1;
        __syncthreads();
        #pragma unroll
        for (int kk = 0; kk < BK; kk++) {
            float4 a0 = *(const float4*)&As[kk][ty * 8];
            float4 a1 = *(const float4*)&As[kk][ty * 8 + 4];
            float4 b0 = *(const float4*)&Bs[kk][tx * 8];
            float4 b1 = *(const float4*)&Bs[kk][tx * 8 + 4];
            float a[8] = {a0.x, a0.y, a0.z, a0.w, a1.x, a1.y, a1.z, a1.w};
            float b[8] = {b0.x, b0.y, b0.z, b0.w, b1.x, b1.y, b1.z, b1.w};
            #pragma unroll
            for (int i = 0; i < 8; i++)
                #pragma unroll
                for (int j = 0; j < 8; j++) acc[i][j] += a[i] * b[j];
        }
        __syncthreads();
    }
    int row0 = bm * BM + ty * 8;
    int col0 = bn * BN + tx * 8;
    #pragma unroll
    for (int i = 0; i < 8; i++) {
        long rbase = (long)(row0 + i) * Dout;
        #pragma unroll
        for (int j = 0; j < 8; j++) {
            int col = col0 + j;
            float v = acc[i][j] + bias[col];
            if (EPI == 1) v = gelu_f(v);
            long idx = rbase + col;
            if (EPI == 2) v += add1[idx] + add2[idx];
            if (EPI == 3) v += add1[idx];
            C[idx] = v;
        }
    }
}

// ---------------- gamma / h_t elementwise ------------------------------------
__global__ void gamma_ht_kernel(const float* __restrict__ t,
                                const float* __restrict__ m2,
                                const float* __restrict__ z,
                                const float* __restrict__ glin,
                                const float* __restrict__ x,
                                float* __restrict__ gamma,
                                float* __restrict__ ht) {
    long i = (long)(blockIdx.x * blockDim.x + threadIdx.x);
    float4 tv = ((const float4*)t)[i];
    float4 mv = ((const float4*)m2)[i];
    float4 zv = ((const float4*)z)[i];
    float4 gv = ((const float4*)glin)[i];
    float4 xv = ((const float4*)x)[i];
    float4 gm, h;
    gm.x = sigmoid_f(tv.x + mv.x); gm.y = sigmoid_f(tv.y + mv.y);
    gm.z = sigmoid_f(tv.z + mv.z); gm.w = sigmoid_f(tv.w + mv.w);
    h.x = zv.x * sigmoid_f(gv.x) + gm.x * xv.x;
    h.y = zv.y * sigmoid_f(gv.y) + gm.y * xv.y;
    h.z = zv.z * sigmoid_f(gv.z) + gm.z * xv.z;
    h.w = zv.w * sigmoid_f(gv.w) + gm.w * xv.w;
    ((float4*)gamma)[i] = gm;
    ((float4*)ht)[i] = h;
}

// ---------------- cumprod (chunked scan over (BH, S, dh) view) ---------------
__global__ void cumprod_local(const float* __restrict__ gamma,
                              float* __restrict__ outp) {
    int c = blockIdx.x, bh = blockIdx.y, d2 = threadIdx.x;
    long base = (long)bh * SEQ * DH + (long)c * CS * DH + d2;
    float p = 1.0f;
    for (int i = 0; i < CS; i++) {
        p *= gamma[base + (long)i * DH];
        outp[base + (long)i * DH] = p;
    }
    g_cp_tot[(bh * NCHUNK + c) * DH + d2] = p;
}
__global__ void cumprod_scan() {
    int lane = blockIdx.x * blockDim.x + threadIdx.x; // NBH*DH = 4096
    int bh = lane / DH, d2 = lane % DH;
    float r = 1.0f;
    for (int c = 0; c < NCHUNK; c++) {
        int idx = (bh * NCHUNK + c) * DH + d2;
        g_cp_pref[idx] = r;
        r *= g_cp_tot[idx];
    }
}
__global__ void cumprod_apply(float* __restrict__ outp) {
    int c = blockIdx.x, bh = blockIdx.y, d2 = threadIdx.x;
    if (c == 0) return;
    float pref = g_cp_pref[(bh * NCHUNK + c) * DH + d2];
    long base = (long)bh * SEQ * DH + (long)c * CS * DH + d2;
    for (int i = 0; i < CS; i++) outp[base + (long)i * DH] *= pref;
}

// ---------------- attention over 64 memory tokens ----------------------------
// grid (S/64, H, B), 256 threads; full softmax (M=64) in smem.
#define ATTN_SMEM ((64*128 + 128*68 + 64*128 + 64*66) * 4)
__global__ void attn_kernel(const float* __restrict__ qa,
                            const float* __restrict__ ka,
                            const float* __restrict__ va,
                            float* __restrict__ ctx) {
    extern __shared__ float sm[];
    float* qs  = sm;                 // [64][128]
    float* kst = qs + 64 * 128;      // [128][68]  (k transposed, padded)
    float* vs  = kst + 128 * 68;     // [64][128]
    float* sc  = vs + 64 * 128;      // [64][66]
    int st = blockIdx.x, h = blockIdx.y, b = blockIdx.z;
    int s0 = st * 64;
    int tid = threadIdx.x;

    for (int l = tid; l < 64 * 32; l += 256) {
        int r = l >> 5, c4 = (l & 31) * 4;
        float4 v = *(const float4*)(qa + (((long)(b * SEQ + s0 + r) * NUM_HEADS + h) << 7) + c4);
        *(float4*)&qs[r * 128 + c4] = v;
    }
    for (int l = tid; l < 64 * 32; l += 256) {
        int m = l >> 5, c4 = (l & 31) * 4;
        float4 v = *(const float4*)(ka + (((long)(b * MEM_TOKENS + m) * NUM_HEADS + h) << 7) + c4);
        kst[(c4 + 0) * 68 + m] = v.x; kst[(c4 + 1) * 68 + m] = v.y;
        kst[(c4 + 2) * 68 + m] = v.z; kst[(c4 + 3) * 68 + m] = v.w;
    }
    for (int l = tid; l < 64 * 32; l += 256) {
        int m = l >> 5, c4 = (l & 31) * 4;
        float4 v = *(const float4*)(va + (((long)(b * MEM_TOKENS + m) * NUM_HEADS + h) << 7) + c4);
        *(float4*)&vs[m * 128 + c4] = v;
    }
    __syncthreads();

    int tx = tid & 15, ty = tid >> 4;
    float acc[4][4];
    #pragma unroll
    for (int i = 0; i < 4; i++)
        #pragma unroll
        for (int j = 0; j < 4; j++) acc[i][j] = 0.0f;
    #pragma unroll 4
    for (int d = 0; d < 128; d++) {
        float4 bv = *(const float4*)&kst[d * 68 + tx * 4];
        float a0 = qs[(ty * 4 + 0) * 128 + d];
        float a1 = qs[(ty * 4 + 1) * 128 + d];
        float a2 = qs[(ty * 4 + 2) * 128 + d];
        float a3 = qs[(ty * 4 + 3) * 128 + d];
        acc[0][0] += a0 * bv.x; acc[0][1] += a0 * bv.y; acc[0][2] += a0 * bv.z; acc[0][3] += a0 * bv.w;
        acc[1][0] += a1 * bv.x; acc[1][1] += a1 * bv.y; acc[1][2] += a1 * bv.z; acc[1][3] += a1 * bv.w;
        acc[2][0] += a2 * bv.x; acc[2][1] += a2 * bv.y; acc[2][2] += a2 * bv.z; acc[2][3] += a2 * bv.w;
        acc[3][0] += a3 * bv.x; acc[3][1] += a3 * bv.y; acc[3][2] += a3 * bv.z; acc[3][3] += a3 * bv.w;
    }
    const float scale = 0.08838834764831845f; // 1/sqrt(128)
    #pragma unroll
    for (int i = 0; i < 4; i++)
        #pragma unroll
        for (int j = 0; j < 4; j++)
            sc[(ty * 4 + i) * 66 + tx * 4 + j] = acc[i][j] * scale;
    __syncthreads();

    if (tid < 64) {
        float* row = &sc[tid * 66];
        float mx = -1e30f;
        for (int m = 0; m < 64; m++) mx = fmaxf(mx, row[m]);
        float s = 0.0f;
        for (int m = 0; m < 64; m++) { float e = expf(row[m] - mx); row[m] = e; s += e; }
        float inv = 1.0f / s;
        for (int m = 0; m < 64; m++) row[m] *= inv;
    }
    __syncthreads();

    float o[4][8];
    #pragma unroll
    for (int i = 0; i < 4; i++)
        #pragma unroll
        for (int j = 0; j < 8; j++) o[i][j] = 0.0f;
    #pragma unroll 4
    for (int m = 0; m < 64; m++) {
        float p0 = sc[(ty * 4 + 0) * 66 + m];
        float p1 = sc[(ty * 4 + 1) * 66 + m];
        float p2 = sc[(ty * 4 + 2) * 66 + m];
        float p3 = sc[(ty * 4 + 3) * 66 + m];
        float4 v0 = *(const float4*)&vs[m * 128 + tx * 8];
        float4 v1 = *(const float4*)&vs[m * 128 + tx * 8 + 4];
        float vv[8] = {v0.x, v0.y, v0.z, v0.w, v1.x, v1.y, v1.z, v1.w};
        #pragma unroll
        for (int j = 0; j < 8; j++) {
            o[0][j] += p0 * vv[j]; o[1][j] += p1 * vv[j];
            o[2][j] += p2 * vv[j]; o[3][j] += p3 * vv[j];
        }
    }
    #pragma unroll
    for (int i = 0; i < 4; i++) {
        long base = (((long)(b * SEQ + s0 + ty * 4 + i) * NUM_HEADS + h) << 7) + tx * 8;
        float4 w0 = {o[i][0], o[i][1], o[i][2], o[i][3]};
        float4 w1 = {o[i][4], o[i][5], o[i][6], o[i][7]};
        *(float4*)(ctx + base)     = w0;
        *(float4*)(ctx + base + 4) = w1;
    }
}

// ---------------- host launcher ----------------------------------------------
extern "C" void kernel_launch(void* const* d_in, const int* in_sizes, int n_in,
                              void* d_out, int out_size) {
    // Detect input ordering: signature order has bq (2048) at index 3,
    // setup_inputs dict order has wk (4.2M) at index 3.
    bool sig = (in_sizes[3] == MODEL_DIM);
    const float *x, *memory, *wk, *bk, *wz, *bz, *wg, *bg, *n1w, *n2w;
    const float *md1, *mb1, *md2, *mb2, *mcw, *mcb;
    const float *awq, *abq, *awk, *abk, *awv, *abv, *awo, *abo;
    const float *f1, *fb1, *f2, *fb2;
    #define IN(i) ((const float*)d_in[(i)])
    if (sig) {
        x = IN(0);  memory = IN(1);
        wk = IN(4);  bk = IN(5);  wz = IN(8);  bz = IN(9);  wg = IN(10); bg = IN(11);
        n1w = IN(12); n2w = IN(13);
        md1 = IN(14); mb1 = IN(15); md2 = IN(16); mb2 = IN(17); mcw = IN(18); mcb = IN(19);
        awq = IN(20); abq = IN(21); awk = IN(22); abk = IN(23); awv = IN(24); abv = IN(25);
        awo = IN(26); abo = IN(27);
        f1 = IN(28); fb1 = IN(29); f2 = IN(30); fb2 = IN(31);
    } else {
        x = IN(0);  memory = IN(1);
        wk = IN(3);  wz = IN(5);  wg = IN(6);
        md1 = IN(7); md2 = IN(8); mcw = IN(9);
        awq = IN(10); awk = IN(11); awv = IN(12); awo = IN(13);
        f1 = IN(14); f2 = IN(15);
        bk = IN(17); bz = IN(19); bg = IN(20);
        mb1 = IN(21); mb2 = IN(22); mcb = IN(23);
        abq = IN(24); abk = IN(25); abv = IN(26); abo = IN(27);
        fb1 = IN(28); fb2 = IN(29);
        n1w = IN(30); n2w = IN(31);
    }
    #undef IN

    float *xn, *kbuf, *zbuf, *glin, *ubuf, *tbuf, *m2buf, *gammab, *htb;
    float *qab, *kab, *vab, *ctxb, *xresb, *xn2b, *a1b;
    cudaGetSymbolAddress((void**)&xn,    g_xn);
    cudaGetSymbolAddress((void**)&kbuf,  g_k);
    cudaGetSymbolAddress((void**)&zbuf,  g_z);
    cudaGetSymbolAddress((void**)&glin,  g_glin);
    cudaGetSymbolAddress((void**)&ubuf,  g_u);
    cudaGetSymbolAddress((void**)&tbuf,  g_t);
    cudaGetSymbolAddress((void**)&m2buf, g_m2);
    cudaGetSymbolAddress((void**)&gammab,g_gamma);
    cudaGetSymbolAddress((void**)&htb,   g_ht);
    cudaGetSymbolAddress((void**)&qab,   g_qa);
    cudaGetSymbolAddress((void**)&kab,   g_ka);
    cudaGetSymbolAddress((void**)&vab,   g_va);
    cudaGetSymbolAddress((void**)&ctxb,  g_ctx);
    cudaGetSymbolAddress((void**)&xresb, g_xres);
    cudaGetSymbolAddress((void**)&xn2b,  g_xn2);
    cudaGetSymbolAddress((void**)&a1b,   g_a1);

    float* out = (float*)d_out;
    float* cum = out + (long)NTOK * MODEL_DIM;

    dim3 gDD(MODEL_DIM / 128, NTOK / 128);   // (16,32)
    dim3 gDI(INNER_DIM / 128, NTOK / 128);   // (4,32)
    dim3 gDF(FFN_DIM / 128,  NTOK / 128);    // (64,32)
    dim3 gMEM(MODEL_DIM / 128, 1);           // memory proj: 128 rows

    // 1) xn = rmsnorm(x, n1w)
    rmsnorm_kernel<<<NTOK, 256>>>(x, n1w, xn);
    // 2) projections
    gemm_kernel<0><<<gDD, 256>>>(xn, wk, bk, kbuf, NTOK, MODEL_DIM, MODEL_DIM, nullptr, nullptr);
    gemm_kernel<0><<<gDD, 256>>>(xn, wz, bz, zbuf, NTOK, MODEL_DIM, MODEL_DIM, nullptr, nullptr);
    gemm_kernel<0><<<gDD, 256>>>(x,  wg, bg, glin, NTOK, MODEL_DIM, MODEL_DIM, nullptr, nullptr);
    // 3) decay net
    gemm_kernel<1><<<gDI, 256>>>(zbuf, md1, mb1, ubuf, NTOK, MODEL_DIM, INNER_DIM, nullptr, nullptr);
    gemm_kernel<0><<<gDD, 256>>>(ubuf, md2, mb2, tbuf, NTOK, INNER_DIM, MODEL_DIM, nullptr, nullptr);
    gemm_kernel<0><<<gDD, 256>>>(kbuf, mcw, mcb, m2buf, NTOK, MODEL_DIM, MODEL_DIM, nullptr, nullptr);
    // 4) gamma = sigmoid(t+m2); h_t = z*sigmoid(glin) + gamma*x
    gamma_ht_kernel<<<(NTOK * MODEL_DIM) / (256 * 4), 256>>>(tbuf, m2buf, zbuf, glin, x, gammab, htb);
    // 5) cumprod (second output)
    cumprod_local<<<dim3(NCHUNK, NBH), DH>>>(gammab, cum);
    cumprod_scan<<<(NBH * DH) / 256, 256>>>();
    cumprod_apply<<<dim3(NCHUNK, NBH), DH>>>(cum);
    // 6) attention
    gemm_kernel<0><<<gDD, 256>>>(htb, awq, abq, qab, NTOK, MODEL_DIM, MODEL_DIM, nullptr, nullptr);
    gemm_kernel<0><<<gMEM, 256>>>(memory, awk, abk, kab, BATCH * MEM_TOKENS, MODEL_DIM, MODEL_DIM, nullptr, nullptr);
    gemm_kernel<0><<<gMEM, 256>>>(memory, awv, abv, vab, BATCH * MEM_TOKENS, MODEL_DIM, MODEL_DIM, nullptr, nullptr);
    cudaFuncSetAttribute(attn_kernel, cudaFuncAttributeMaxDynamicSharedMemorySize, ATTN_SMEM);
    attn_kernel<<<dim3(SEQ / 64, NUM_HEADS, BATCH), 256, ATTN_SMEM>>>(qab, kab, vab, ctxb);
    // 7) x_res = x + h_t + (ctx@awo + abo)
    gemm_kernel<2><<<gDD, 256>>>(ctxb, awo, abo, xresb, NTOK, MODEL_DIM, MODEL_DIM, x, htb);
    // 8) FFN + residual -> first output
    rmsnorm_kernel<<<NTOK, 256>>>(xresb, n2w, xn2b);
    gemm_kernel<1><<<gDF, 256>>>(xn2b, f1, fb1, a1b, NTOK, MODEL_DIM, FFN_DIM, nullptr, nullptr);
    gemm_kernel<3><<<gDD, 256>>>(a1b, f2, fb2, out, NTOK, FFN_DIM, MODEL_DIM, xresb, nullptr);
}

// round 4
// speedup vs baseline: 2.4676x; 2.4676x over previous
#include <cuda_runtime.h>
#include <cuda_bf16.h>
#include <math.h>
#include <stdint.h>

#define MODEL_DIM 2048
#define INNER_DIM 512
#define NUM_HEADS 16
#define FFN_DIM   8192
#define MEM_TOKENS 64
#define BATCH 2
#define SEQ   2048
#define NTOK  (BATCH*SEQ)            // 4096
#define DH    (MODEL_DIM/NUM_HEADS)  // 128
#define EPSV  1e-6f

#define NCHUNK 32
#define CS     (SEQ/NCHUNK)          // 64
#define NBH    (BATCH*NUM_HEADS)     // 32

// ---------------- fp32 scratch ------------------------------------------------
__device__ float g_xn   [NTOK*MODEL_DIM];
__device__ float g_k    [NTOK*MODEL_DIM];
__device__ float g_z    [NTOK*MODEL_DIM];
__device__ float g_glin [NTOK*MODEL_DIM];
__device__ float g_u    [NTOK*INNER_DIM];
__device__ float g_t    [NTOK*MODEL_DIM];
__device__ float g_m2   [NTOK*MODEL_DIM];
__device__ float g_gamma[NTOK*MODEL_DIM];
__device__ float g_ht   [NTOK*MODEL_DIM];
__device__ float g_qa   [NTOK*MODEL_DIM];
__device__ float g_ka   [BATCH*MEM_TOKENS*MODEL_DIM];
__device__ float g_va   [BATCH*MEM_TOKENS*MODEL_DIM];
__device__ float g_ctx  [NTOK*MODEL_DIM];
__device__ float g_xres [NTOK*MODEL_DIM];
__device__ float g_xn2  [NTOK*MODEL_DIM];
__device__ float g_a1   [NTOK*FFN_DIM];
__device__ float g_cp_tot [NBH*NCHUNK*DH];
__device__ float g_cp_pref[NBH*NCHUNK*DH];

// ---------------- split-bf16 transposed weights (hi/lo planes) ----------------
#define DD (MODEL_DIM*MODEL_DIM)
__device__ __nv_bfloat16 g_wkH[DD],  g_wkL[DD];
__device__ __nv_bfloat16 g_wzH[DD],  g_wzL[DD];
__device__ __nv_bfloat16 g_wgH[DD],  g_wgL[DD];
__device__ __nv_bfloat16 g_mcwH[DD], g_mcwL[DD];
__device__ __nv_bfloat16 g_awqH[DD], g_awqL[DD];
__device__ __nv_bfloat16 g_awkH[DD], g_awkL[DD];
__device__ __nv_bfloat16 g_awvH[DD], g_awvL[DD];
__device__ __nv_bfloat16 g_awoH[DD], g_awoL[DD];
__device__ __nv_bfloat16 g_md1H[MODEL_DIM*INNER_DIM], g_md1L[MODEL_DIM*INNER_DIM];
__device__ __nv_bfloat16 g_md2H[INNER_DIM*MODEL_DIM], g_md2L[INNER_DIM*MODEL_DIM];
__device__ __nv_bfloat16 g_f1H[MODEL_DIM*FFN_DIM],    g_f1L[MODEL_DIM*FFN_DIM];
__device__ __nv_bfloat16 g_f2H[FFN_DIM*MODEL_DIM],    g_f2L[FFN_DIM*MODEL_DIM];

// ---------------- helpers --------------------------------------------------
__device__ __forceinline__ uint32_t smem_to_u32(const void* p) {
    uint32_t a;
    asm("{ .reg .u64 t; cvta.to.shared.u64 t, %1; cvt.u32.u64 %0, t; }" : "=r"(a) : "l"(p));
    return a;
}
#define SMEM_SWIZZLE_128B(o) ((o) ^ (((o) >> 3) & 0x70))

__device__ __forceinline__ float gelu_f(float v) {
    float t = 0.7978845608028654f * (v + 0.044715f * v * v * v);
    return 0.5f * v * (1.0f + tanhf(t));
}
__device__ __forceinline__ float sigmoid_f(float v) { return 1.0f / (1.0f + expf(-v)); }

__device__ __forceinline__ void mma16816(float* c, const uint32_t* a, const uint32_t* b) {
    asm volatile("mma.sync.aligned.m16n8k16.row.col.f32.bf16.bf16.f32 "
        "{%0,%1,%2,%3}, {%4,%5,%6,%7}, {%8,%9}, {%0,%1,%2,%3};"
        : "+f"(c[0]), "+f"(c[1]), "+f"(c[2]), "+f"(c[3])
        : "r"(a[0]), "r"(a[1]), "r"(a[2]), "r"(a[3]), "r"(b[0]), "r"(b[1]));
}
#define LDMATRIX_X4(r0, r1, r2, r3, addr) \
    asm volatile("ldmatrix.sync.aligned.m8n8.x4.shared.b16 {%0,%1,%2,%3}, [%4];" \
        : "=r"(r0), "=r"(r1), "=r"(r2), "=r"(r3) : "r"(addr))
#define CP_ASYNC_16(dst, src) \
    asm volatile("cp.async.cg.shared.global [%0], [%1], 16;" :: "r"(dst), "l"(src))
#define CP_COMMIT()  asm volatile("cp.async.commit_group;" ::: "memory")
#define CP_WAIT_ALL() asm volatile("cp.async.wait_group 0;" ::: "memory")

// ---------------- weight transpose + split: W[K,D] -> H/L[D,K] bf16 ------------
__global__ void split_transpose(const float* __restrict__ W,
                                __nv_bfloat16* __restrict__ H,
                                __nv_bfloat16* __restrict__ L, int K, int D) {
    __shared__ float t[32][33];
    int d0 = blockIdx.x * 32, k0 = blockIdx.y * 32;
    int tx = threadIdx.x, ty = threadIdx.y;     // 32 x 8
    #pragma unroll
    for (int i = 0; i < 32; i += 8)
        t[ty + i][tx] = W[(size_t)(k0 + ty + i) * D + d0 + tx];
    __syncthreads();
    #pragma unroll
    for (int i = 0; i < 32; i += 8) {
        float v = t[tx][ty + i];                // W[k0+tx][d0+ty+i]
        __nv_bfloat16 h = __float2bfloat16_rn(v);
        __nv_bfloat16 l = __float2bfloat16_rn(v - __bfloat162float(h));
        size_t o = (size_t)(d0 + ty + i) * K + k0 + tx;
        H[o] = h; L[o] = l;
    }
}

// ---------------- HMMA GEMM: C[M,Dout] = A[M,K] @ Wplanes^T + bias (+epi) ------
// CTA tile 128x128, BK=64. Split-bf16 3-pass (AhBh + AhBl + AlBh), fp32 accum.
// EPI: 0 none, 1 gelu, 2 +add1+add2, 3 +add1
#define HG_STAGE 65536
#define HG_SMEM  (2*HG_STAGE)
#define OFF_AH 0
#define OFF_AL 16384
#define OFF_BH 32768
#define OFF_BL 49152

template <int EPI>
__global__ void __launch_bounds__(256, 1)
hmma_gemm(const float* __restrict__ A,
          const __nv_bfloat16* __restrict__ BH,
          const __nv_bfloat16* __restrict__ BL,
          const float* __restrict__ bias,
          float* __restrict__ C,
          int K, int Dout,
          const float* __restrict__ add1,
          const float* __restrict__ add2) {
    extern __shared__ __align__(1024) char sm[];
    uint32_t sb = smem_to_u32(sm);
    int tid = threadIdx.x;
    int wid = tid >> 5, lane = tid & 31;
    int wm = wid & 1, wn = wid >> 1;   // warps: 2 (M) x 4 (N); warp tile 64x32

    const float* Ab = A + (size_t)blockIdx.y * 128 * K;
    const __nv_bfloat16* BHb = BH + (size_t)blockIdx.x * 128 * K;
    const __nv_bfloat16* BLb = BL + (size_t)blockIdx.x * 128 * K;

    float acc[4][4][4];
    #pragma unroll
    for (int i = 0; i < 4; i++)
        #pragma unroll
        for (int j = 0; j < 4; j++)
            #pragma unroll
            for (int q = 0; q < 4; q++) acc[i][j][q] = 0.0f;

    // A staging: 128x64 fp32 = 2048 float4; 8 per thread
    float4 av[8];
    int NS = K >> 6;

    // ---- prologue: LDG A(0); cp.async B(0) into buf0
    {
        #pragma unroll
        for (int i = 0; i < 8; i++) {
            int idx = tid + i * 256;
            int r = idx >> 4, kq = idx & 15;
            av[i] = *(const float4*)(Ab + (size_t)r * K + kq * 4);
        }
        // B tile: 128 rows x 8 16B-units per plane = 1024 units -> 4 per thread
        #pragma unroll
        for (int i = 0; i < 4; i++) {
            int idx = tid + i * 256;
            int r = idx >> 3, u = idx & 7;
            uint32_t sw = SMEM_SWIZZLE_128B((uint32_t)(r * 128 + u * 16));
            CP_ASYNC_16(sb + OFF_BH + sw, BHb + (size_t)r * K + u * 8);
            CP_ASYNC_16(sb + OFF_BL + sw, BLb + (size_t)r * K + u * 8);
        }
        CP_COMMIT();
    }

    for (int s = 0; s < NS; s++) {
        int p = s & 1;
        uint32_t soff = (uint32_t)p * HG_STAGE;
        // 1) STS A(s) from regs (split hi/lo)
        #pragma unroll
        for (int i = 0; i < 8; i++) {
            int idx = tid + i * 256;
            int r = idx >> 4, kq = idx & 15;
            float4 v = av[i];
            __nv_bfloat16 h0 = __float2bfloat16_rn(v.x);
            __nv_bfloat16 h1 = __float2bfloat16_rn(v.y);
            __nv_bfloat16 h2 = __float2bfloat16_rn(v.z);
            __nv_bfloat16 h3 = __float2bfloat16_rn(v.w);
            __nv_bfloat16 l0 = __float2bfloat16_rn(v.x - __bfloat162float(h0));
            __nv_bfloat16 l1 = __float2bfloat16_rn(v.y - __bfloat162float(h1));
            __nv_bfloat16 l2 = __float2bfloat16_rn(v.z - __bfloat162float(h2));
            __nv_bfloat16 l3 = __float2bfloat16_rn(v.w - __bfloat162float(h3));
            uint2 hh, ll;
            hh.x = (uint32_t)__bfloat16_as_ushort(h0) | ((uint32_t)__bfloat16_as_ushort(h1) << 16);
            hh.y = (uint32_t)__bfloat16_as_ushort(h2) | ((uint32_t)__bfloat16_as_ushort(h3) << 16);
            ll.x = (uint32_t)__bfloat16_as_ushort(l0) | ((uint32_t)__bfloat16_as_ushort(l1) << 16);
            ll.y = (uint32_t)__bfloat16_as_ushort(l2) | ((uint32_t)__bfloat16_as_ushort(l3) << 16);
            uint32_t sw = SMEM_SWIZZLE_128B((uint32_t)(r * 128 + kq * 8));
            *(uint2*)(sm + soff + OFF_AH + sw) = hh;
            *(uint2*)(sm + soff + OFF_AL + sw) = ll;
        }
        // 2) prefetch A(s+1) into regs
        if (s + 1 < NS) {
            int k0 = (s + 1) << 6;
            #pragma unroll
            for (int i = 0; i < 8; i++) {
                int idx = tid + i * 256;
                int r = idx >> 4, kq = idx & 15;
                av[i] = *(const float4*)(Ab + (size_t)r * K + k0 + kq * 4);
            }
        }
        // 3) B(s) arrived; make STS visible
        CP_WAIT_ALL();
        __syncthreads();
        // 4) issue B(s+1)
        if (s + 1 < NS) {
            int k0 = (s + 1) << 6;
            uint32_t soff2 = (uint32_t)(p ^ 1) * HG_STAGE;
            #pragma unroll
            for (int i = 0; i < 4; i++) {
                int idx = tid + i * 256;
                int r = idx >> 3, u = idx & 7;
                uint32_t sw = SMEM_SWIZZLE_128B((uint32_t)(r * 128 + u * 16));
                CP_ASYNC_16(sb + soff2 + OFF_BH + sw, BHb + (size_t)r * K + k0 + u * 8);
                CP_ASYNC_16(sb + soff2 + OFF_BL + sw, BLb + (size_t)r * K + k0 + u * 8);
            }
            CP_COMMIT();
        }
        // 5) compute on buf p
        uint32_t aH = sb + soff + OFF_AH;
        uint32_t aL = sb + soff + OFF_AL;
        uint32_t bH = sb + soff + OFF_BH;
        uint32_t bL = sb + soff + OFF_BL;
        #pragma unroll
        for (int ks = 0; ks < 4; ks++) {
            uint32_t ah[4][4], al[4][4], bh[4][2], bl[4][2];
            #pragma unroll
            for (int i = 0; i < 4; i++) {
                int row = wm * 64 + i * 16 + (lane & 15);
                int kb = ks * 32 + (lane >> 4) * 16;
                uint32_t sw = SMEM_SWIZZLE_128B((uint32_t)(row * 128 + kb));
                LDMATRIX_X4(ah[i][0], ah[i][1], ah[i][2], ah[i][3], aH + sw);
                LDMATRIX_X4(al[i][0], al[i][1], al[i][2], al[i][3], aL + sw);
            }
            #pragma unroll
            for (int jp = 0; jp < 2; jp++) {
                int n = wn * 32 + jp * 16 + (lane >> 4) * 8 + (lane & 7);
                int kb = ks * 32 + ((lane >> 3) & 1) * 16;
                uint32_t sw = SMEM_SWIZZLE_128B((uint32_t)(n * 128 + kb));
                LDMATRIX_X4(bh[2*jp][0], bh[2*jp][1], bh[2*jp+1][0], bh[2*jp+1][1], bH + sw);
                LDMATRIX_X4(bl[2*jp][0], bl[2*jp][1], bl[2*jp+1][0], bl[2*jp+1][1], bL + sw);
            }
            #pragma unroll
            for (int i = 0; i < 4; i++)
                #pragma unroll
                for (int j = 0; j < 4; j++) {
                    mma16816(acc[i][j], ah[i], bh[j]);
                    mma16816(acc[i][j], ah[i], bl[j]);
                    mma16816(acc[i][j], al[i], bh[j]);
                }
        }
        __syncthreads();
    }

    // ---- epilogue
    int gr = lane >> 2;        // 0..7
    int gc = (lane & 3) * 2;   // 0,2,4,6
    #pragma unroll
    for (int i = 0; i < 4; i++) {
        int row0 = blockIdx.y * 128 + wm * 64 + i * 16 + gr;
        #pragma unroll
        for (int j = 0; j < 4; j++) {
            int col = blockIdx.x * 128 + wn * 32 + j * 8 + gc;
            float2 bv = *(const float2*)(bias + col);
            #pragma unroll
            for (int half = 0; half < 2; half++) {
                int row = row0 + half * 8;
                size_t idx = (size_t)row * Dout + col;
                float2 o;
                o.x = acc[i][j][half * 2 + 0] + bv.x;
                o.y = acc[i][j][half * 2 + 1] + bv.y;
                if (EPI == 1) { o.x = gelu_f(o.x); o.y = gelu_f(o.y); }
                if (EPI == 2) {
                    float2 a1 = *(const float2*)(add1 + idx);
                    float2 a2 = *(const float2*)(add2 + idx);
                    o.x += a1.x + a2.x; o.y += a1.y + a2.y;
                }
                if (EPI == 3) {
                    float2 a1 = *(const float2*)(add1 + idx);
                    o.x += a1.x; o.y += a1.y;
                }
                *(float2*)(C + idx) = o;
            }
        }
    }
}

// ---------------- RMSNorm -------------------------------------------------------
__global__ void rmsnorm_kernel(const float* __restrict__ x,
                               const float* __restrict__ w,
                               float* __restrict__ out) {
    int row = blockIdx.x;
    int t = threadIdx.x;
    const float4* xr = (const float4*)(x + (long)row * MODEL_DIM);
    float4 v0 = xr[t];
    float4 v1 = xr[t + 256];
    float s = v0.x*v0.x + v0.y*v0.y + v0.z*v0.z + v0.w*v0.w
            + v1.x*v1.x + v1.y*v1.y + v1.z*v1.z + v1.w*v1.w;
    #pragma unroll
    for (int o = 16; o > 0; o >>= 1) s += __shfl_xor_sync(0xffffffffu, s, o);
    __shared__ float red[8];
    if ((t & 31) == 0) red[t >> 5] = s;
    __syncthreads();
    float tot = red[0]+red[1]+red[2]+red[3]+red[4]+red[5]+red[6]+red[7];
    float inv = 1.0f / (sqrtf(tot / (float)MODEL_DIM) + EPSV);
    const float4* wr = (const float4*)w;
    float4 w0 = wr[t], w1 = wr[t + 256];
    float4 o0, o1;
    o0.x = w0.x*v0.x*inv; o0.y = w0.y*v0.y*inv; o0.z = w0.z*v0.z*inv; o0.w = w0.w*v0.w*inv;
    o1.x = w1.x*v1.x*inv; o1.y = w1.y*v1.y*inv; o1.z = w1.z*v1.z*inv; o1.w = w1.w*v1.w*inv;
    float4* orow = (float4*)(out + (long)row * MODEL_DIM);
    orow[t] = o0; orow[t + 256] = o1;
}

// ---------------- gamma / h_t elementwise ---------------------------------------
__global__ void gamma_ht_kernel(const float* __restrict__ t,
                                const float* __restrict__ m2,
                                const float* __restrict__ z,
                                const float* __restrict__ glin,
                                const float* __restrict__ x,
                                float* __restrict__ gamma,
                                float* __restrict__ ht) {
    long i = (long)(blockIdx.x * blockDim.x + threadIdx.x);
    float4 tv = ((const float4*)t)[i];
    float4 mv = ((const float4*)m2)[i];
    float4 zv = ((const float4*)z)[i];
    float4 gv = ((const float4*)glin)[i];
    float4 xv = ((const float4*)x)[i];
    float4 gm, h;
    gm.x = sigmoid_f(tv.x + mv.x); gm.y = sigmoid_f(tv.y + mv.y);
    gm.z = sigmoid_f(tv.z + mv.z); gm.w = sigmoid_f(tv.w + mv.w);
    h.x = zv.x * sigmoid_f(gv.x) + gm.x * xv.x;
    h.y = zv.y * sigmoid_f(gv.y) + gm.y * xv.y;
    h.z = zv.z * sigmoid_f(gv.z) + gm.z * xv.z;
    h.w = zv.w * sigmoid_f(gv.w) + gm.w * xv.w;
    ((float4*)gamma)[i] = gm;
    ((float4*)ht)[i] = h;
}

// ---------------- cumprod -------------------------------------------------------
__global__ void cumprod_local(const float* __restrict__ gamma, float* __restrict__ outp) {
    int c = blockIdx.x, bh = blockIdx.y, d2 = threadIdx.x;
    long base = (long)bh * SEQ * DH + (long)c * CS * DH + d2;
    float p = 1.0f;
    for (int i = 0; i < CS; i++) {
        p *= gamma[base + (long)i * DH];
        outp[base + (long)i * DH] = p;
    }
    g_cp_tot[(bh * NCHUNK + c) * DH + d2] = p;
}
__global__ void cumprod_scan() {
    int lane = blockIdx.x * blockDim.x + threadIdx.x;
    int bh = lane / DH, d2 = lane % DH;
    float r = 1.0f;
    for (int c = 0; c < NCHUNK; c++) {
        int idx = (bh * NCHUNK + c) * DH + d2;
        g_cp_pref[idx] = r;
        r *= g_cp_tot[idx];
    }
}
__global__ void cumprod_apply(float* __restrict__ outp) {
    int c = blockIdx.x, bh = blockIdx.y, d2 = threadIdx.x;
    if (c == 0) return;
    float pref = g_cp_pref[(bh * NCHUNK + c) * DH + d2];
    long base = (long)bh * SEQ * DH + (long)c * CS * DH + d2;
    for (int i = 0; i < CS; i++) outp[base + (long)i * DH] *= pref;
}

// ---------------- attention over 64 memory tokens --------------------------------
#define ATTN_SMEM ((64*128 + 128*68 + 64*128 + 64*66) * 4)
__global__ void attn_kernel(const float* __restrict__ qa,
                            const float* __restrict__ ka,
                            const float* __restrict__ va,
                            float* __restrict__ ctx) {
    extern __shared__ float smf[];
    float* qs  = smf;
    float* kst = qs + 64 * 128;
    float* vs  = kst + 128 * 68;
    float* sc  = vs + 64 * 128;
    int st = blockIdx.x, h = blockIdx.y, b = blockIdx.z;
    int s0 = st * 64;
    int tid = threadIdx.x;

    for (int l = tid; l < 64 * 32; l += 256) {
        int r = l >> 5, c4 = (l & 31) * 4;
        float4 v = *(const float4*)(qa + (((long)(b * SEQ + s0 + r) * NUM_HEADS + h) << 7) + c4);
        *(float4*)&qs[r * 128 + c4] = v;
    }
    for (int l = tid; l < 64 * 32; l += 256) {
        int m = l >> 5, c4 = (l & 31) * 4;
        float4 v = *(const float4*)(ka + (((long)(b * MEM_TOKENS + m) * NUM_HEADS + h) << 7) + c4);
        kst[(c4 + 0) * 68 + m] = v.x; kst[(c4 + 1) * 68 + m] = v.y;
        kst[(c4 + 2) * 68 + m] = v.z; kst[(c4 + 3) * 68 + m] = v.w;
    }
    for (int l = tid; l < 64 * 32; l += 256) {
        int m = l >> 5, c4 = (l & 31) * 4;
        float4 v = *(const float4*)(va + (((long)(b * MEM_TOKENS + m) * NUM_HEADS + h) << 7) + c4);
        *(float4*)&vs[m * 128 + c4] = v;
    }
    __syncthreads();

    int tx = tid & 15, ty = tid >> 4;
    float acc[4][4];
    #pragma unroll
    for (int i = 0; i < 4; i++)
        #pragma unroll
        for (int j = 0; j < 4; j++) acc[i][j] = 0.0f;
    #pragma unroll 4
    for (int d = 0; d < 128; d++) {
        float4 bv = *(const float4*)&kst[d * 68 + tx * 4];
        float a0 = qs[(ty * 4 + 0) * 128 + d];
        float a1 = qs[(ty * 4 + 1) * 128 + d];
        float a2 = qs[(ty * 4 + 2) * 128 + d];
        float a3 = qs[(ty * 4 + 3) * 128 + d];
        acc[0][0] += a0 * bv.x; acc[0][1] += a0 * bv.y; acc[0][2] += a0 * bv.z; acc[0][3] += a0 * bv.w;
        acc[1][0] += a1 * bv.x; acc[1][1] += a1 * bv.y; acc[1][2] += a1 * bv.z; acc[1][3] += a1 * bv.w;
        acc[2][0] += a2 * bv.x; acc[2][1] += a2 * bv.y; acc[2][2] += a2 * bv.z; acc[2][3] += a2 * bv.w;
        acc[3][0] += a3 * bv.x; acc[3][1] += a3 * bv.y; acc[3][2] += a3 * bv.z; acc[3][3] += a3 * bv.w;
    }
    const float scale = 0.08838834764831845f;
    #pragma unroll
    for (int i = 0; i < 4; i++)
        #pragma unroll
        for (int j = 0; j < 4; j++)
            sc[(ty * 4 + i) * 66 + tx * 4 + j] = acc[i][j] * scale;
    __syncthreads();

    if (tid < 64) {
        float* row = &sc[tid * 66];
        float mx = -1e30f;
        for (int m = 0; m < 64; m++) mx = fmaxf(mx, row[m]);
        float s = 0.0f;
        for (int m = 0; m < 64; m++) { float e = expf(row[m] - mx); row[m] = e; s += e; }
        float inv = 1.0f / s;
        for (int m = 0; m < 64; m++) row[m] *= inv;
    }
    __syncthreads();

    float o[4][8];
    #pragma unroll
    for (int i = 0; i < 4; i++)
        #pragma unroll
        for (int j = 0; j < 8; j++) o[i][j] = 0.0f;
    #pragma unroll 4
    for (int m = 0; m < 64; m++) {
        float p0 = sc[(ty * 4 + 0) * 66 + m];
        float p1 = sc[(ty * 4 + 1) * 66 + m];
        float p2 = sc[(ty * 4 + 2) * 66 + m];
        float p3 = sc[(ty * 4 + 3) * 66 + m];
        float4 v0 = *(const float4*)&vs[m * 128 + tx * 8];
        float4 v1 = *(const float4*)&vs[m * 128 + tx * 8 + 4];
        float vv[8] = {v0.x, v0.y, v0.z, v0.w, v1.x, v1.y, v1.z, v1.w};
        #pragma unroll
        for (int j = 0; j < 8; j++) {
            o[0][j] += p0 * vv[j]; o[1][j] += p1 * vv[j];
            o[2][j] += p2 * vv[j]; o[3][j] += p3 * vv[j];
        }
    }
    #pragma unroll
    for (int i = 0; i < 4; i++) {
        long base = (((long)(b * SEQ + s0 + ty * 4 + i) * NUM_HEADS + h) << 7) + tx * 8;
        float4 w0 = {o[i][0], o[i][1], o[i][2], o[i][3]};
        float4 w1 = {o[i][4], o[i][5], o[i][6], o[i][7]};
        *(float4*)(ctx + base)     = w0;
        *(float4*)(ctx + base + 4) = w1;
    }
}

// ---------------- host launcher ---------------------------------------------------
extern "C" void kernel_launch(void* const* d_in, const int* in_sizes, int n_in,
                              void* d_out, int out_size) {
    bool sig = (in_sizes[3] == MODEL_DIM);
    const float *x, *memory, *wk, *bk, *wz, *bz, *wg, *bg, *n1w, *n2w;
    const float *md1, *mb1, *md2, *mb2, *mcw, *mcb;
    const float *awq, *abq, *awk, *abk, *awv, *abv, *awo, *abo;
    const float *f1, *fb1, *f2, *fb2;
    #define IN(i) ((const float*)d_in[(i)])
    if (sig) {
        x = IN(0);  memory = IN(1);
        wk = IN(4);  bk = IN(5);  wz = IN(8);  bz = IN(9);  wg = IN(10); bg = IN(11);
        n1w = IN(12); n2w = IN(13);
        md1 = IN(14); mb1 = IN(15); md2 = IN(16); mb2 = IN(17); mcw = IN(18); mcb = IN(19);
        awq = IN(20); abq = IN(21); awk = IN(22); abk = IN(23); awv = IN(24); abv = IN(25);
        awo = IN(26); abo = IN(27);
        f1 = IN(28); fb1 = IN(29); f2 = IN(30); fb2 = IN(31);
    } else {
        x = IN(0);  memory = IN(1);
        wk = IN(3);  wz = IN(5);  wg = IN(6);
        md1 = IN(7); md2 = IN(8); mcw = IN(9);
        awq = IN(10); awk = IN(11); awv = IN(12); awo = IN(13);
        f1 = IN(14); f2 = IN(15);
        bk = IN(17); bz = IN(19); bg = IN(20);
        mb1 = IN(21); mb2 = IN(22); mcb = IN(23);
        abq = IN(24); abk = IN(25); abv = IN(26); abo = IN(27);
        fb1 = IN(28); fb2 = IN(29);
        n1w = IN(30); n2w = IN(31);
    }
    #undef IN

    float *xn, *kbuf, *zbuf, *glin, *ubuf, *tbuf, *m2buf, *gammab, *htb;
    float *qab, *kab, *vab, *ctxb, *xresb, *xn2b, *a1b;
    cudaGetSymbolAddress((void**)&xn,    g_xn);
    cudaGetSymbolAddress((void**)&kbuf,  g_k);
    cudaGetSymbolAddress((void**)&zbuf,  g_z);
    cudaGetSymbolAddress((void**)&glin,  g_glin);
    cudaGetSymbolAddress((void**)&ubuf,  g_u);
    cudaGetSymbolAddress((void**)&tbuf,  g_t);
    cudaGetSymbolAddress((void**)&m2buf, g_m2);
    cudaGetSymbolAddress((void**)&gammab,g_gamma);
    cudaGetSymbolAddress((void**)&htb,   g_ht);
    cudaGetSymbolAddress((void**)&qab,   g_qa);
    cudaGetSymbolAddress((void**)&kab,   g_ka);
    cudaGetSymbolAddress((void**)&vab,   g_va);
    cudaGetSymbolAddress((void**)&ctxb,  g_ctx);
    cudaGetSymbolAddress((void**)&xresb, g_xres);
    cudaGetSymbolAddress((void**)&xn2b,  g_xn2);
    cudaGetSymbolAddress((void**)&a1b,   g_a1);

    __nv_bfloat16 *wkH,*wkL,*wzH,*wzL,*wgH,*wgL,*mcwH,*mcwL;
    __nv_bfloat16 *awqH,*awqL,*awkH,*awkL,*awvH,*awvL,*awoH,*awoL;
    __nv_bfloat16 *md1H,*md1L,*md2H,*md2L,*f1H,*f1L,*f2H,*f2L;
    cudaGetSymbolAddress((void**)&wkH,  g_wkH);  cudaGetSymbolAddress((void**)&wkL,  g_wkL);
    cudaGetSymbolAddress((void**)&wzH,  g_wzH);  cudaGetSymbolAddress((void**)&wzL,  g_wzL);
    cudaGetSymbolAddress((void**)&wgH,  g_wgH);  cudaGetSymbolAddress((void**)&wgL,  g_wgL);
    cudaGetSymbolAddress((void**)&mcwH, g_mcwH); cudaGetSymbolAddress((void**)&mcwL, g_mcwL);
    cudaGetSymbolAddress((void**)&awqH, g_awqH); cudaGetSymbolAddress((void**)&awqL, g_awqL);
    cudaGetSymbolAddress((void**)&awkH, g_awkH); cudaGetSymbolAddress((void**)&awkL, g_awkL);
    cudaGetSymbolAddress((void**)&awvH, g_awvH); cudaGetSymbolAddress((void**)&awvL, g_awvL);
    cudaGetSymbolAddress((void**)&awoH, g_awoH); cudaGetSymbolAddress((void**)&awoL, g_awoL);
    cudaGetSymbolAddress((void**)&md1H, g_md1H); cudaGetSymbolAddress((void**)&md1L, g_md1L);
    cudaGetSymbolAddress((void**)&md2H, g_md2H); cudaGetSymbolAddress((void**)&md2L, g_md2L);
    cudaGetSymbolAddress((void**)&f1H,  g_f1H);  cudaGetSymbolAddress((void**)&f1L,  g_f1L);
    cudaGetSymbolAddress((void**)&f2H,  g_f2H);  cudaGetSymbolAddress((void**)&f2L,  g_f2L);

    float* out = (float*)d_out;
    float* cum = out + (long)NTOK * MODEL_DIM;

    cudaFuncSetAttribute(hmma_gemm<0>, cudaFuncAttributeMaxDynamicSharedMemorySize, HG_SMEM);
    cudaFuncSetAttribute(hmma_gemm<1>, cudaFuncAttributeMaxDynamicSharedMemorySize, HG_SMEM);
    cudaFuncSetAttribute(hmma_gemm<2>, cudaFuncAttributeMaxDynamicSharedMemorySize, HG_SMEM);
    cudaFuncSetAttribute(hmma_gemm<3>, cudaFuncAttributeMaxDynamicSharedMemorySize, HG_SMEM);
    cudaFuncSetAttribute(attn_kernel, cudaFuncAttributeMaxDynamicSharedMemorySize, ATTN_SMEM);

    dim3 tb(32, 8);
    dim3 gT(MODEL_DIM / 32, MODEL_DIM / 32);
    split_transpose<<<gT, tb>>>(wk,  wkH,  wkL,  MODEL_DIM, MODEL_DIM);
    split_transpose<<<gT, tb>>>(wz,  wzH,  wzL,  MODEL_DIM, MODEL_DIM);
    split_transpose<<<gT, tb>>>(wg,  wgH,  wgL,  MODEL_DIM, MODEL_DIM);
    split_transpose<<<gT, tb>>>(mcw, mcwH, mcwL, MODEL_DIM, MODEL_DIM);
    split_transpose<<<gT, tb>>>(awq, awqH, awqL, MODEL_DIM, MODEL_DIM);
    split_transpose<<<gT, tb>>>(awk, awkH, awkL, MODEL_DIM, MODEL_DIM);
    split_transpose<<<gT, tb>>>(awv, awvH, awvL, MODEL_DIM, MODEL_DIM);
    split_transpose<<<gT, tb>>>(awo, awoH, awoL, MODEL_DIM, MODEL_DIM);
    split_transpose<<<dim3(INNER_DIM / 32, MODEL_DIM / 32), tb>>>(md1, md1H, md1L, MODEL_DIM, INNER_DIM);
    split_transpose<<<dim3(MODEL_DIM / 32, INNER_DIM / 32), tb>>>(md2, md2H, md2L, INNER_DIM, MODEL_DIM);
    split_transpose<<<dim3(FFN_DIM / 32,  MODEL_DIM / 32), tb>>>(f1, f1H, f1L, MODEL_DIM, FFN_DIM);
    split_transpose<<<dim3(MODEL_DIM / 32, FFN_DIM / 32),  tb>>>(f2, f2H, f2L, FFN_DIM, MODEL_DIM);

    dim3 gDD(MODEL_DIM / 128, NTOK / 128);   // (16, 32)
    dim3 gDI(INNER_DIM / 128, NTOK / 128);   // (4, 32)
    dim3 gDF(FFN_DIM / 128,  NTOK / 128);    // (64, 32)
    dim3 gMEM(MODEL_DIM / 128, 1);           // memory proj: 128 rows

    // 1) xn = rmsnorm(x, n1w)
    rmsnorm_kernel<<<NTOK, 256>>>(x, n1w, xn);
    // 2) projections
    hmma_gemm<0><<<gDD, 256, HG_SMEM>>>(xn, wkH, wkL, bk, kbuf, MODEL_DIM, MODEL_DIM, nullptr, nullptr);
    hmma_gemm<0><<<gDD, 256, HG_SMEM>>>(xn, wzH, wzL, bz, zbuf, MODEL_DIM, MODEL_DIM, nullptr, nullptr);
    hmma_gemm<0><<<gDD, 256, HG_SMEM>>>(x,  wgH, wgL, bg, glin, MODEL_DIM, MODEL_DIM, nullptr, nullptr);
    // 3) decay net
    hmma_gemm<1><<<gDI, 256, HG_SMEM>>>(zbuf, md1H, md1L, mb1, ubuf, MODEL_DIM, INNER_DIM, nullptr, nullptr);
    hmma_gemm<0><<<gDD, 256, HG_SMEM>>>(ubuf, md2H, md2L, mb2, tbuf, INNER_DIM, MODEL_DIM, nullptr, nullptr);
    hmma_gemm<0><<<gDD, 256, HG_SMEM>>>(kbuf, mcwH, mcwL, mcb, m2buf, MODEL_DIM, MODEL_DIM, nullptr, nullptr);
    // 4) gamma = sigmoid(t+m2); h_t = z*sigmoid(glin) + gamma*x
    gamma_ht_kernel<<<(NTOK * MODEL_DIM) / (256 * 4), 256>>>(tbuf, m2buf, zbuf, glin, x, gammab, htb);
    // 5) cumprod (second output)
    cumprod_local<<<dim3(NCHUNK, NBH), DH>>>(gammab, cum);
    cumprod_scan<<<(NBH * DH) / 256, 256>>>();
    cumprod_apply<<<dim3(NCHUNK, NBH), DH>>>(cum);
    // 6) attention
    hmma_gemm<0><<<gDD, 256, HG_SMEM>>>(htb, awqH, awqL, abq, qab, MODEL_DIM, MODEL_DIM, nullptr, nullptr);
    hmma_gemm<0><<<gMEM, 256, HG_SMEM>>>(memory, awkH, awkL, abk, kab, MODEL_DIM, MODEL_DIM, nullptr, nullptr);
    hmma_gemm<0><<<gMEM, 256, HG_SMEM>>>(memory, awvH, awvL, abv, vab, MODEL_DIM, MODEL_DIM, nullptr, nullptr);
    attn_kernel<<<dim3(SEQ / 64, NUM_HEADS, BATCH), 256, ATTN_SMEM>>>(qab, kab, vab, ctxb);
    // 7) x_res = x + h_t + (ctx@awo + abo)
    hmma_gemm<2><<<gDD, 256, HG_SMEM>>>(ctxb, awoH, awoL, abo, xresb, MODEL_DIM, MODEL_DIM, x, htb);
    // 8) FFN + residual -> first output
    rmsnorm_kernel<<<NTOK, 256>>>(xresb, n2w, xn2b);
    hmma_gemm<1><<<gDF, 256, HG_SMEM>>>(xn2b, f1H, f1L, fb1, a1b, MODEL_DIM, FFN_DIM, nullptr, nullptr);
    hmma_gemm<3><<<gDD, 256, HG_SMEM>>>(a1b, f2H, f2L, fb2, out, FFN_DIM, MODEL_DIM, xresb, nullptr);
}

// round 5
// speedup vs baseline: 4.5133x; 1.8291x over previous
#include <cuda_runtime.h>
#include <cuda_fp16.h>
#include <math.h>
#include <stdint.h>

#define MODEL_DIM 2048
#define INNER_DIM 512
#define NUM_HEADS 16
#define FFN_DIM   8192
#define MEM_TOKENS 64
#define BATCH 2
#define SEQ   2048
#define NTOK  (BATCH*SEQ)            // 4096
#define DH    (MODEL_DIM/NUM_HEADS)  // 128
#define EPSV  1e-6f

#define NCHUNK 32
#define CS     (SEQ/NCHUNK)          // 64
#define NBH    (BATCH*NUM_HEADS)     // 32

// ---------------- fp32 scratch -------------------------------------------------
__device__ float g_z    [NTOK*MODEL_DIM];
__device__ float g_glin [NTOK*MODEL_DIM];
__device__ float g_t    [NTOK*MODEL_DIM];
__device__ float g_m2   [NTOK*MODEL_DIM];
__device__ float g_gamma[NTOK*MODEL_DIM];
__device__ float g_ht   [NTOK*MODEL_DIM];
__device__ float g_qa   [NTOK*MODEL_DIM];
__device__ float g_kv   [BATCH*MEM_TOKENS*2*MODEL_DIM];   // [128, 4096] k|v
__device__ float g_xres [NTOK*MODEL_DIM];
__device__ float g_kvbias[2*MODEL_DIM];
__device__ float g_cp_tot [NBH*NCHUNK*DH];
__device__ float g_cp_pref[NBH*NCHUNK*DH];

// ---------------- fp16 activation planes (hi/lo) -------------------------------
__device__ __half g_xH  [NTOK*MODEL_DIM], g_xL  [NTOK*MODEL_DIM];
__device__ __half g_xnH [NTOK*MODEL_DIM], g_xnL [NTOK*MODEL_DIM];
__device__ __half g_zH  [NTOK*MODEL_DIM], g_zL  [NTOK*MODEL_DIM];
__device__ __half g_kH  [NTOK*MODEL_DIM], g_kL  [NTOK*MODEL_DIM];
__device__ __half g_uH  [NTOK*INNER_DIM], g_uL  [NTOK*INNER_DIM];
__device__ __half g_htH [NTOK*MODEL_DIM], g_htL [NTOK*MODEL_DIM];
__device__ __half g_memH[BATCH*MEM_TOKENS*MODEL_DIM], g_memL[BATCH*MEM_TOKENS*MODEL_DIM];
__device__ __half g_ctxH[NTOK*MODEL_DIM], g_ctxL[NTOK*MODEL_DIM];
__device__ __half g_xn2H[NTOK*MODEL_DIM], g_xn2L[NTOK*MODEL_DIM];
__device__ __half g_a1H [NTOK*FFN_DIM],   g_a1L [NTOK*FFN_DIM];

// ---------------- fp16 transposed weights [Dout, K] ----------------------------
#define DD (MODEL_DIM*MODEL_DIM)
__device__ __half g_wk [DD], g_wz [DD], g_wg [DD], g_mcw[DD];
__device__ __half g_awq[DD], g_awo[DD];
__device__ __half g_awkv[2*MODEL_DIM*MODEL_DIM];          // rows 0..2047 = awk, 2048..4095 = awv
__device__ __half g_md1[MODEL_DIM*INNER_DIM];             // [512, 2048]
__device__ __half g_md2[INNER_DIM*MODEL_DIM];             // [2048, 512]
__device__ __half g_f1 [MODEL_DIM*FFN_DIM];               // [8192, 2048]
__device__ __half g_f2 [FFN_DIM*MODEL_DIM];               // [2048, 8192]

// ---------------- helpers -------------------------------------------------------
__device__ __forceinline__ uint32_t smem_to_u32(const void* p) {
    uint32_t a;
    asm("{ .reg .u64 t; cvta.to.shared.u64 t, %1; cvt.u32.u64 %0, t; }" : "=r"(a) : "l"(p));
    return a;
}
#define SMEM_SWIZZLE_128B(o) ((o) ^ (((o) >> 3) & 0x70))

__device__ __forceinline__ float gelu_f(float v) {
    float t = 0.7978845608028654f * (v + 0.044715f * v * v * v);
    return 0.5f * v * (1.0f + tanhf(t));
}
__device__ __forceinline__ float sigmoid_f(float v) { return 1.0f / (1.0f + expf(-v)); }
__device__ __forceinline__ void split_h(float v, __half& h, __half& l) {
    h = __float2half_rn(v);
    l = __float2half_rn(v - __half2float(h));
}

__device__ __forceinline__ void mma16816h(float* c, const uint32_t* a, const uint32_t* b) {
    asm volatile("mma.sync.aligned.m16n8k16.row.col.f32.f16.f16.f32 "
        "{%0,%1,%2,%3}, {%4,%5,%6,%7}, {%8,%9}, {%0,%1,%2,%3};"
        : "+f"(c[0]), "+f"(c[1]), "+f"(c[2]), "+f"(c[3])
        : "r"(a[0]), "r"(a[1]), "r"(a[2]), "r"(a[3]), "r"(b[0]), "r"(b[1]));
}
#define LDMATRIX_X4(r0, r1, r2, r3, addr) \
    asm volatile("ldmatrix.sync.aligned.m8n8.x4.shared.b16 {%0,%1,%2,%3}, [%4];" \
        : "=r"(r0), "=r"(r1), "=r"(r2), "=r"(r3) : "r"(addr))
#define CP_ASYNC_16(dst, src) \
    asm volatile("cp.async.cg.shared.global [%0], [%1], 16;" :: "r"(dst), "l"(src))
#define CP_COMMIT()  asm volatile("cp.async.commit_group;" ::: "memory")
#define CP_WAIT(n)   asm volatile("cp.async.wait_group %0;" :: "n"(n) : "memory")

// ---------------- weight transpose: W[K,D] -> T[D,K] fp16 -----------------------
__global__ void transpose_h(const float* __restrict__ W, __half* __restrict__ T,
                            int K, int D) {
    __shared__ float t[32][33];
    int d0 = blockIdx.x * 32, k0 = blockIdx.y * 32;
    int tx = threadIdx.x, ty = threadIdx.y;     // 32 x 8
    #pragma unroll
    for (int i = 0; i < 32; i += 8)
        t[ty + i][tx] = W[(size_t)(k0 + ty + i) * D + d0 + tx];
    __syncthreads();
    #pragma unroll
    for (int i = 0; i < 32; i += 8) {
        float v = t[tx][ty + i];
        T[(size_t)(d0 + ty + i) * K + k0 + tx] = __float2half_rn(v);
    }
}

// ---------------- fp32 -> hi/lo fp16 planes -------------------------------------
__global__ void split2_kernel(const float* __restrict__ src,
                              __half* __restrict__ H, __half* __restrict__ L) {
    size_t i = (size_t)(blockIdx.x * blockDim.x + threadIdx.x);
    float4 v = ((const float4*)src)[i];
    __half h0, h1, h2, h3, l0, l1, l2, l3;
    split_h(v.x, h0, l0); split_h(v.y, h1, l1);
    split_h(v.z, h2, l2); split_h(v.w, h3, l3);
    ((__half2*)H)[i * 2 + 0] = __halves2half2(h0, h1);
    ((__half2*)H)[i * 2 + 1] = __halves2half2(h2, h3);
    ((__half2*)L)[i * 2 + 0] = __halves2half2(l0, l1);
    ((__half2*)L)[i * 2 + 1] = __halves2half2(l2, l3);
}

__global__ void concat_bias(const float* __restrict__ a, const float* __restrict__ b) {
    int i = blockIdx.x * blockDim.x + threadIdx.x;
    g_kvbias[i] = (i < MODEL_DIM) ? a[i] : b[i - MODEL_DIM];
}

// ---------------- fp16 2-pass HMMA GEMM ------------------------------------------
// C[M,Dout] = (AH+AL)[M,K] @ W[Dout,K]^T + bias, W single fp16 plane.
// Tile 128 x BN, BK=64, 8 warps (2M x 4N), 2-stage cp.async.
// EPI: 0 none, 1 gelu, 2 +add1+add2, 3 +add1
template <int BN>
__device__ __forceinline__ void hg_issue(uint32_t base,
        const __half* AHb, const __half* ALb, const __half* Bb,
        int K, int k0, int tid) {
    #pragma unroll
    for (int i = 0; i < 4; i++) {           // A planes: 1024 units each
        int idx = tid + i * 256;
        int r = idx >> 3, u = idx & 7;
        uint32_t sw = SMEM_SWIZZLE_128B((uint32_t)(r * 128 + u * 16));
        CP_ASYNC_16(base + sw,         AHb + (size_t)r * K + k0 + u * 8);
        CP_ASYNC_16(base + 16384 + sw, ALb + (size_t)r * K + k0 + u * 8);
    }
    #pragma unroll
    for (int i = 0; i < (BN * 8) / 256; i++) {  // B plane: BN*8 units
        int idx = tid + i * 256;
        int r = idx >> 3, u = idx & 7;
        uint32_t sw = SMEM_SWIZZLE_128B((uint32_t)(r * 128 + u * 16));
        CP_ASYNC_16(base + 32768 + sw, Bb + (size_t)r * K + k0 + u * 8);
    }
    CP_COMMIT();
}

template <int BN, int EPI, bool WF32, bool WPL>
__global__ void __launch_bounds__(256, 1)
hgemm(const __half* __restrict__ AH, const __half* __restrict__ AL,
      const __half* __restrict__ Bp, const float* __restrict__ bias,
      float* __restrict__ C, __half* __restrict__ PH, __half* __restrict__ PL,
      int K, int Dout, const float* __restrict__ add1, const float* __restrict__ add2) {
    constexpr int NJ = BN / 32;
    constexpr int STAGE = 32768 + BN * 128;
    extern __shared__ __align__(1024) char sm[];
    uint32_t sb = smem_to_u32(sm);
    int tid = threadIdx.x;
    int wid = tid >> 5, lane = tid & 31;
    int wm = wid & 1, wn = wid >> 1;       // 2 (M) x 4 (N) warps

    const __half* AHb = AH + (size_t)blockIdx.y * 128 * K;
    const __half* ALb = AL + (size_t)blockIdx.y * 128 * K;
    const __half* Bb  = Bp + (size_t)blockIdx.x * BN * K;

    float acc[4][NJ][4];
    #pragma unroll
    for (int i = 0; i < 4; i++)
        #pragma unroll
        for (int j = 0; j < NJ; j++)
            #pragma unroll
            for (int q = 0; q < 4; q++) acc[i][j][q] = 0.0f;

    int NS = K >> 6;
    hg_issue<BN>(sb,         AHb, ALb, Bb, K, 0,  tid);
    hg_issue<BN>(sb + STAGE, AHb, ALb, Bb, K, 64, tid);

    for (int s = 0; s < NS; s++) {
        if (s + 1 < NS) { CP_WAIT(1); } else { CP_WAIT(0); }
        __syncthreads();
        uint32_t aH = sb + (uint32_t)(s & 1) * STAGE;
        uint32_t aL = aH + 16384;
        uint32_t bB = aH + 32768;
        #pragma unroll
        for (int ks = 0; ks < 4; ks++) {
            uint32_t ah[4][4], al[4][4], bf[NJ][2];
            #pragma unroll
            for (int i = 0; i < 4; i++) {
                int row = wm * 64 + i * 16 + (lane & 15);
                int kb = ks * 32 + (lane >> 4) * 16;
                uint32_t sw = SMEM_SWIZZLE_128B((uint32_t)(row * 128 + kb));
                LDMATRIX_X4(ah[i][0], ah[i][1], ah[i][2], ah[i][3], aH + sw);
                LDMATRIX_X4(al[i][0], al[i][1], al[i][2], al[i][3], aL + sw);
            }
            #pragma unroll
            for (int jp = 0; jp < NJ / 2; jp++) {
                int n = wn * (BN / 4) + jp * 16 + (lane >> 4) * 8 + (lane & 7);
                int kb = ks * 32 + ((lane >> 3) & 1) * 16;
                uint32_t sw = SMEM_SWIZZLE_128B((uint32_t)(n * 128 + kb));
                LDMATRIX_X4(bf[2*jp][0], bf[2*jp][1], bf[2*jp+1][0], bf[2*jp+1][1], bB + sw);
            }
            #pragma unroll
            for (int i = 0; i < 4; i++)
                #pragma unroll
                for (int j = 0; j < NJ; j++) mma16816h(acc[i][j], ah[i], bf[j]);
            #pragma unroll
            for (int i = 0; i < 4; i++)
                #pragma unroll
                for (int j = 0; j < NJ; j++) mma16816h(acc[i][j], al[i], bf[j]);
        }
        __syncthreads();
        if (s + 2 < NS)
            hg_issue<BN>(sb + (uint32_t)(s & 1) * STAGE, AHb, ALb, Bb, K, (s + 2) * 64, tid);
    }

    // ---- epilogue
    int gr = lane >> 2;        // 0..7
    int gc = (lane & 3) * 2;   // 0,2,4,6
    #pragma unroll
    for (int i = 0; i < 4; i++) {
        int row0 = blockIdx.y * 128 + wm * 64 + i * 16 + gr;
        #pragma unroll
        for (int j = 0; j < NJ; j++) {
            int col = blockIdx.x * BN + wn * (BN / 4) + j * 8 + gc;
            float2 bv = *(const float2*)(bias + col);
            #pragma unroll
            for (int half = 0; half < 2; half++) {
                int row = row0 + half * 8;
                size_t idx = (size_t)row * Dout + col;
                float2 o;
                o.x = acc[i][j][half * 2 + 0] + bv.x;
                o.y = acc[i][j][half * 2 + 1] + bv.y;
                if (EPI == 1) { o.x = gelu_f(o.x); o.y = gelu_f(o.y); }
                if (EPI == 2) {
                    float2 a1 = *(const float2*)(add1 + idx);
                    float2 a2 = *(const float2*)(add2 + idx);
                    o.x += a1.x + a2.x; o.y += a1.y + a2.y;
                }
                if (EPI == 3) {
                    float2 a1 = *(const float2*)(add1 + idx);
                    o.x += a1.x; o.y += a1.y;
                }
                if (WF32) *(float2*)(C + idx) = o;
                if (WPL) {
                    __half hx, lx, hy, ly;
                    split_h(o.x, hx, lx); split_h(o.y, hy, ly);
                    *(__half2*)(PH + idx) = __halves2half2(hx, hy);
                    *(__half2*)(PL + idx) = __halves2half2(lx, ly);
                }
            }
        }
    }
}

// ---------------- RMSNorm -> fp16 planes ----------------------------------------
__global__ void rmsnorm_planes(const float* __restrict__ x,
                               const float* __restrict__ w,
                               __half* __restrict__ H, __half* __restrict__ L) {
    int row = blockIdx.x;
    int t = threadIdx.x;  // 256
    const float4* xr = (const float4*)(x + (size_t)row * MODEL_DIM);
    float4 v0 = xr[t];
    float4 v1 = xr[t + 256];
    float s = v0.x*v0.x + v0.y*v0.y + v0.z*v0.z + v0.w*v0.w
            + v1.x*v1.x + v1.y*v1.y + v1.z*v1.z + v1.w*v1.w;
    #pragma unroll
    for (int o = 16; o > 0; o >>= 1) s += __shfl_xor_sync(0xffffffffu, s, o);
    __shared__ float red[8];
    if ((t & 31) == 0) red[t >> 5] = s;
    __syncthreads();
    float tot = red[0]+red[1]+red[2]+red[3]+red[4]+red[5]+red[6]+red[7];
    float inv = 1.0f / (sqrtf(tot / (float)MODEL_DIM) + EPSV);
    const float4* wr = (const float4*)w;
    float4 w0 = wr[t], w1 = wr[t + 256];
    float o0[4] = {w0.x*v0.x*inv, w0.y*v0.y*inv, w0.z*v0.z*inv, w0.w*v0.w*inv};
    float o1[4] = {w1.x*v1.x*inv, w1.y*v1.y*inv, w1.z*v1.z*inv, w1.w*v1.w*inv};
    __half2* Hr = (__half2*)(H + (size_t)row * MODEL_DIM);
    __half2* Lr = (__half2*)(L + (size_t)row * MODEL_DIM);
    __half h0,h1,h2,h3,l0,l1,l2,l3;
    split_h(o0[0],h0,l0); split_h(o0[1],h1,l1); split_h(o0[2],h2,l2); split_h(o0[3],h3,l3);
    Hr[t*2]   = __halves2half2(h0,h1); Hr[t*2+1] = __halves2half2(h2,h3);
    Lr[t*2]   = __halves2half2(l0,l1); Lr[t*2+1] = __halves2half2(l2,l3);
    split_h(o1[0],h0,l0); split_h(o1[1],h1,l1); split_h(o1[2],h2,l2); split_h(o1[3],h3,l3);
    Hr[512+t*2]   = __halves2half2(h0,h1); Hr[512+t*2+1] = __halves2half2(h2,h3);
    Lr[512+t*2]   = __halves2half2(l0,l1); Lr[512+t*2+1] = __halves2half2(l2,l3);
}

// ---------------- gamma / h_t elementwise (+ ht planes) ---------------------------
__global__ void gamma_ht_kernel(const float* __restrict__ t,
                                const float* __restrict__ m2,
                                const float* __restrict__ z,
                                const float* __restrict__ glin,
                                const float* __restrict__ x,
                                float* __restrict__ gamma,
                                float* __restrict__ ht,
                                __half* __restrict__ htH, __half* __restrict__ htL) {
    size_t i = (size_t)(blockIdx.x * blockDim.x + threadIdx.x);
    float4 tv = ((const float4*)t)[i];
    float4 mv = ((const float4*)m2)[i];
    float4 zv = ((const float4*)z)[i];
    float4 gv = ((const float4*)glin)[i];
    float4 xv = ((const float4*)x)[i];
    float4 gm, h;
    gm.x = sigmoid_f(tv.x + mv.x); gm.y = sigmoid_f(tv.y + mv.y);
    gm.z = sigmoid_f(tv.z + mv.z); gm.w = sigmoid_f(tv.w + mv.w);
    h.x = zv.x * sigmoid_f(gv.x) + gm.x * xv.x;
    h.y = zv.y * sigmoid_f(gv.y) + gm.y * xv.y;
    h.z = zv.z * sigmoid_f(gv.z) + gm.z * xv.z;
    h.w = zv.w * sigmoid_f(gv.w) + gm.w * xv.w;
    ((float4*)gamma)[i] = gm;
    ((float4*)ht)[i] = h;
    __half h0,h1,h2,h3,l0,l1,l2,l3;
    split_h(h.x,h0,l0); split_h(h.y,h1,l1); split_h(h.z,h2,l2); split_h(h.w,h3,l3);
    ((__half2*)htH)[i*2]   = __halves2half2(h0,h1);
    ((__half2*)htH)[i*2+1] = __halves2half2(h2,h3);
    ((__half2*)htL)[i*2]   = __halves2half2(l0,l1);
    ((__half2*)htL)[i*2+1] = __halves2half2(l2,l3);
}

// ---------------- cumprod ---------------------------------------------------------
__global__ void cumprod_local(const float* __restrict__ gamma, float* __restrict__ outp) {
    int c = blockIdx.x, bh = blockIdx.y, d2 = threadIdx.x;
    size_t base = (size_t)bh * SEQ * DH + (size_t)c * CS * DH + d2;
    float p = 1.0f;
    for (int i = 0; i < CS; i++) {
        p *= gamma[base + (size_t)i * DH];
        outp[base + (size_t)i * DH] = p;
    }
    g_cp_tot[(bh * NCHUNK + c) * DH + d2] = p;
}
__global__ void cumprod_scan() {
    int lane = blockIdx.x * blockDim.x + threadIdx.x;
    int bh = lane / DH, d2 = lane % DH;
    float r = 1.0f;
    for (int c = 0; c < NCHUNK; c++) {
        int idx = (bh * NCHUNK + c) * DH + d2;
        g_cp_pref[idx] = r;
        r *= g_cp_tot[idx];
    }
}
__global__ void cumprod_apply(float* __restrict__ outp) {
    int c = blockIdx.x, bh = blockIdx.y, d2 = threadIdx.x;
    if (c == 0) return;
    float pref = g_cp_pref[(bh * NCHUNK + c) * DH + d2];
    size_t base = (size_t)bh * SEQ * DH + (size_t)c * CS * DH + d2;
    for (int i = 0; i < CS; i++) outp[base + (size_t)i * DH] *= pref;
}

// ---------------- attention over 64 memory tokens (out -> fp16 planes) ------------
#define ATTN_SMEM ((64*128 + 128*68 + 64*128 + 64*66) * 4)
__global__ void attn_kernel(const float* __restrict__ qa,
                            const float* __restrict__ kv,
                            __half* __restrict__ ctxH, __half* __restrict__ ctxL) {
    extern __shared__ float smf[];
    float* qs  = smf;
    float* kst = qs + 64 * 128;
    float* vs  = kst + 128 * 68;
    float* sc  = vs + 64 * 128;
    int st = blockIdx.x, h = blockIdx.y, b = blockIdx.z;
    int s0 = st * 64;
    int tid = threadIdx.x;

    for (int l = tid; l < 64 * 32; l += 256) {
        int r = l >> 5, c4 = (l & 31) * 4;
        float4 v = *(const float4*)(qa + (size_t)(b * SEQ + s0 + r) * MODEL_DIM + h * 128 + c4);
        *(float4*)&qs[r * 128 + c4] = v;
    }
    for (int l = tid; l < 64 * 32; l += 256) {
        int m = l >> 5, c4 = (l & 31) * 4;
        float4 v = *(const float4*)(kv + (size_t)(b * MEM_TOKENS + m) * (2 * MODEL_DIM) + h * 128 + c4);
        kst[(c4 + 0) * 68 + m] = v.x; kst[(c4 + 1) * 68 + m] = v.y;
        kst[(c4 + 2) * 68 + m] = v.z; kst[(c4 + 3) * 68 + m] = v.w;
    }
    for (int l = tid; l < 64 * 32; l += 256) {
        int m = l >> 5, c4 = (l & 31) * 4;
        float4 v = *(const float4*)(kv + (size_t)(b * MEM_TOKENS + m) * (2 * MODEL_DIM)
                                    + MODEL_DIM + h * 128 + c4);
        *(float4*)&vs[m * 128 + c4] = v;
    }
    __syncthreads();

    int tx = tid & 15, ty = tid >> 4;
    float acc[4][4];
    #pragma unroll
    for (int i = 0; i < 4; i++)
        #pragma unroll
        for (int j = 0; j < 4; j++) acc[i][j] = 0.0f;
    #pragma unroll 4
    for (int d = 0; d < 128; d++) {
        float4 bv = *(const float4*)&kst[d * 68 + tx * 4];
        float a0 = qs[(ty * 4 + 0) * 128 + d];
        float a1 = qs[(ty * 4 + 1) * 128 + d];
        float a2 = qs[(ty * 4 + 2) * 128 + d];
        float a3 = qs[(ty * 4 + 3) * 128 + d];
        acc[0][0] += a0 * bv.x; acc[0][1] += a0 * bv.y; acc[0][2] += a0 * bv.z; acc[0][3] += a0 * bv.w;
        acc[1][0] += a1 * bv.x; acc[1][1] += a1 * bv.y; acc[1][2] += a1 * bv.z; acc[1][3] += a1 * bv.w;
        acc[2][0] += a2 * bv.x; acc[2][1] += a2 * bv.y; acc[2][2] += a2 * bv.z; acc[2][3] += a2 * bv.w;
        acc[3][0] += a3 * bv.x; acc[3][1] += a3 * bv.y; acc[3][2] += a3 * bv.z; acc[3][3] += a3 * bv.w;
    }
    const float scale = 0.08838834764831845f;
    #pragma unroll
    for (int i = 0; i < 4; i++)
        #pragma unroll
        for (int j = 0; j < 4; j++)
            sc[(ty * 4 + i) * 66 + tx * 4 + j] = acc[i][j] * scale;
    __syncthreads();

    if (tid < 64) {
        float* row = &sc[tid * 66];
        float mx = -1e30f;
        for (int m = 0; m < 64; m++) mx = fmaxf(mx, row[m]);
        float s = 0.0f;
        for (int m = 0; m < 64; m++) { float e = expf(row[m] - mx); row[m] = e; s += e; }
        float inv = 1.0f / s;
        for (int m = 0; m < 64; m++) row[m] *= inv;
    }
    __syncthreads();

    float o[4][8];
    #pragma unroll
    for (int i = 0; i < 4; i++)
        #pragma unroll
        for (int j = 0; j < 8; j++) o[i][j] = 0.0f;
    #pragma unroll 4
    for (int m = 0; m < 64; m++) {
        float p0 = sc[(ty * 4 + 0) * 66 + m];
        float p1 = sc[(ty * 4 + 1) * 66 + m];
        float p2 = sc[(ty * 4 + 2) * 66 + m];
        float p3 = sc[(ty * 4 + 3) * 66 + m];
        float4 v0 = *(const float4*)&vs[m * 128 + tx * 8];
        float4 v1 = *(const float4*)&vs[m * 128 + tx * 8 + 4];
        float vv[8] = {v0.x, v0.y, v0.z, v0.w, v1.x, v1.y, v1.z, v1.w};
        #pragma unroll
        for (int j = 0; j < 8; j++) {
            o[0][j] += p0 * vv[j]; o[1][j] += p1 * vv[j];
            o[2][j] += p2 * vv[j]; o[3][j] += p3 * vv[j];
        }
    }
    #pragma unroll
    for (int i = 0; i < 4; i++) {
        size_t base = (size_t)(b * SEQ + s0 + ty * 4 + i) * MODEL_DIM + h * 128 + tx * 8;
        #pragma unroll
        for (int jp = 0; jp < 4; jp++) {
            __half h0, h1, l0, l1;
            split_h(o[i][jp * 2 + 0], h0, l0);
            split_h(o[i][jp * 2 + 1], h1, l1);
            *(__half2*)(ctxH + base + jp * 2) = __halves2half2(h0, h1);
            *(__half2*)(ctxL + base + jp * 2) = __halves2half2(l0, l1);
        }
    }
}

// ---------------- host launcher -----------------------------------------------------
extern "C" void kernel_launch(void* const* d_in, const int* in_sizes, int n_in,
                              void* d_out, int out_size) {
    bool sig = (in_sizes[3] == MODEL_DIM);
    const float *x, *memory, *wk, *bk, *wz, *bz, *wg, *bg, *n1w, *n2w;
    const float *md1, *mb1, *md2, *mb2, *mcw, *mcb;
    const float *awq, *abq, *awk, *abk, *awv, *abv, *awo, *abo;
    const float *f1, *fb1, *f2, *fb2;
    #define IN(i) ((const float*)d_in[(i)])
    if (sig) {
        x = IN(0);  memory = IN(1);
        wk = IN(4);  bk = IN(5);  wz = IN(8);  bz = IN(9);  wg = IN(10); bg = IN(11);
        n1w = IN(12); n2w = IN(13);
        md1 = IN(14); mb1 = IN(15); md2 = IN(16); mb2 = IN(17); mcw = IN(18); mcb = IN(19);
        awq = IN(20); abq = IN(21); awk = IN(22); abk = IN(23); awv = IN(24); abv = IN(25);
        awo = IN(26); abo = IN(27);
        f1 = IN(28); fb1 = IN(29); f2 = IN(30); fb2 = IN(31);
    } else {
        x = IN(0);  memory = IN(1);
        wk = IN(3);  wz = IN(5);  wg = IN(6);
        md1 = IN(7); md2 = IN(8); mcw = IN(9);
        awq = IN(10); awk = IN(11); awv = IN(12); awo = IN(13);
        f1 = IN(14); f2 = IN(15);
        bk = IN(17); bz = IN(19); bg = IN(20);
        mb1 = IN(21); mb2 = IN(22); mcb = IN(23);
        abq = IN(24); abk = IN(25); abv = IN(26); abo = IN(27);
        fb1 = IN(28); fb2 = IN(29);
        n1w = IN(30); n2w = IN(31);
    }
    #undef IN

    float *zb, *glin, *tb, *m2b, *gammab, *htb, *qab, *kvb, *xresb, *kvbias;
    cudaGetSymbolAddress((void**)&zb,    g_z);
    cudaGetSymbolAddress((void**)&glin,  g_glin);
    cudaGetSymbolAddress((void**)&tb,    g_t);
    cudaGetSymbolAddress((void**)&m2b,   g_m2);
    cudaGetSymbolAddress((void**)&gammab,g_gamma);
    cudaGetSymbolAddress((void**)&htb,   g_ht);
    cudaGetSymbolAddress((void**)&qab,   g_qa);
    cudaGetSymbolAddress((void**)&kvb,   g_kv);
    cudaGetSymbolAddress((void**)&xresb, g_xres);
    cudaGetSymbolAddress((void**)&kvbias,g_kvbias);

    __half *xH,*xL,*xnH,*xnL,*zH,*zL,*kH,*kL,*uH,*uL,*htH,*htL,*memH,*memL,*ctxH,*ctxL,*xn2H,*xn2L,*a1H,*a1L;
    cudaGetSymbolAddress((void**)&xH,  g_xH);   cudaGetSymbolAddress((void**)&xL,  g_xL);
    cudaGetSymbolAddress((void**)&xnH, g_xnH);  cudaGetSymbolAddress((void**)&xnL, g_xnL);
    cudaGetSymbolAddress((void**)&zH,  g_zH);   cudaGetSymbolAddress((void**)&zL,  g_zL);
    cudaGetSymbolAddress((void**)&kH,  g_kH);   cudaGetSymbolAddress((void**)&kL,  g_kL);
    cudaGetSymbolAddress((void**)&uH,  g_uH);   cudaGetSymbolAddress((void**)&uL,  g_uL);
    cudaGetSymbolAddress((void**)&htH, g_htH);  cudaGetSymbolAddress((void**)&htL, g_htL);
    cudaGetSymbolAddress((void**)&memH,g_memH); cudaGetSymbolAddress((void**)&memL,g_memL);
    cudaGetSymbolAddress((void**)&ctxH,g_ctxH); cudaGetSymbolAddress((void**)&ctxL,g_ctxL);
    cudaGetSymbolAddress((void**)&xn2H,g_xn2H); cudaGetSymbolAddress((void**)&xn2L,g_xn2L);
    cudaGetSymbolAddress((void**)&a1H, g_a1H);  cudaGetSymbolAddress((void**)&a1L, g_a1L);

    __half *wkT,*wzT,*wgT,*mcwT,*awqT,*awoT,*awkvT,*md1T,*md2T,*f1T,*f2T;
    cudaGetSymbolAddress((void**)&wkT,  g_wk);
    cudaGetSymbolAddress((void**)&wzT,  g_wz);
    cudaGetSymbolAddress((void**)&wgT,  g_wg);
    cudaGetSymbolAddress((void**)&mcwT, g_mcw);
    cudaGetSymbolAddress((void**)&awqT, g_awq);
    cudaGetSymbolAddress((void**)&awoT, g_awo);
    cudaGetSymbolAddress((void**)&awkvT,g_awkv);
    cudaGetSymbolAddress((void**)&md1T, g_md1);
    cudaGetSymbolAddress((void**)&md2T, g_md2);
    cudaGetSymbolAddress((void**)&f1T,  g_f1);
    cudaGetSymbolAddress((void**)&f2T,  g_f2);

    float* out = (float*)d_out;
    float* cum = out + (size_t)NTOK * MODEL_DIM;

    const int SM256 = 32768 + 256 * 128;   // stage bytes BN=256
    const int SM128 = 32768 + 128 * 128;
    cudaFuncSetAttribute((const void*)hgemm<256,0,false,true>,  cudaFuncAttributeMaxDynamicSharedMemorySize, 2*SM256);
    cudaFuncSetAttribute((const void*)hgemm<256,0,true,true>,   cudaFuncAttributeMaxDynamicSharedMemorySize, 2*SM256);
    cudaFuncSetAttribute((const void*)hgemm<256,0,true,false>,  cudaFuncAttributeMaxDynamicSharedMemorySize, 2*SM256);
    cudaFuncSetAttribute((const void*)hgemm<256,1,false,true>,  cudaFuncAttributeMaxDynamicSharedMemorySize, 2*SM256);
    cudaFuncSetAttribute((const void*)hgemm<256,2,true,false>,  cudaFuncAttributeMaxDynamicSharedMemorySize, 2*SM256);
    cudaFuncSetAttribute((const void*)hgemm<256,3,true,false>,  cudaFuncAttributeMaxDynamicSharedMemorySize, 2*SM256);
    cudaFuncSetAttribute((const void*)hgemm<128,1,false,true>,  cudaFuncAttributeMaxDynamicSharedMemorySize, 2*SM128);
    cudaFuncSetAttribute((const void*)hgemm<128,0,true,false>,  cudaFuncAttributeMaxDynamicSharedMemorySize, 2*SM128);
    cudaFuncSetAttribute(attn_kernel, cudaFuncAttributeMaxDynamicSharedMemorySize, ATTN_SMEM);

    // ---- weight transposes (fp16 single plane)
    dim3 tb8(32, 8);
    dim3 gT(MODEL_DIM / 32, MODEL_DIM / 32);
    transpose_h<<<gT, tb8>>>(wk,  wkT,  MODEL_DIM, MODEL_DIM);
    transpose_h<<<gT, tb8>>>(wz,  wzT,  MODEL_DIM, MODEL_DIM);
    transpose_h<<<gT, tb8>>>(wg,  wgT,  MODEL_DIM, MODEL_DIM);
    transpose_h<<<gT, tb8>>>(mcw, mcwT, MODEL_DIM, MODEL_DIM);
    transpose_h<<<gT, tb8>>>(awq, awqT, MODEL_DIM, MODEL_DIM);
    transpose_h<<<gT, tb8>>>(awo, awoT, MODEL_DIM, MODEL_DIM);
    transpose_h<<<gT, tb8>>>(awk, awkvT,                          MODEL_DIM, MODEL_DIM);
    transpose_h<<<gT, tb8>>>(awv, awkvT + (size_t)MODEL_DIM*MODEL_DIM, MODEL_DIM, MODEL_DIM);
    transpose_h<<<dim3(INNER_DIM / 32, MODEL_DIM / 32), tb8>>>(md1, md1T, MODEL_DIM, INNER_DIM);
    transpose_h<<<dim3(MODEL_DIM / 32, INNER_DIM / 32), tb8>>>(md2, md2T, INNER_DIM, MODEL_DIM);
    transpose_h<<<dim3(FFN_DIM / 32,  MODEL_DIM / 32), tb8>>>(f1, f1T, MODEL_DIM, FFN_DIM);
    transpose_h<<<dim3(MODEL_DIM / 32, FFN_DIM / 32),  tb8>>>(f2, f2T, FFN_DIM, MODEL_DIM);
    concat_bias<<<(2 * MODEL_DIM) / 256, 256>>>(abk, abv);

    // ---- activation planes for raw inputs
    split2_kernel<<<(NTOK * MODEL_DIM / 4) / 256, 256>>>(x, xH, xL);
    split2_kernel<<<(BATCH * MEM_TOKENS * MODEL_DIM / 4) / 64, 64>>>(memory, memH, memL);

    dim3 gDD(MODEL_DIM / 256, NTOK / 128);   // (8, 32)
    dim3 gDF(FFN_DIM / 256,  NTOK / 128);    // (32, 32)

    // 1) xn = rmsnorm(x, n1w)  -> planes
    rmsnorm_planes<<<NTOK, 256>>>(x, n1w, xnH, xnL);
    // 2) projections
    hgemm<256,0,false,true><<<gDD, 256, 2*SM256>>>(xnH, xnL, wkT, bk, nullptr, kH, kL, MODEL_DIM, MODEL_DIM, nullptr, nullptr);
    hgemm<256,0,true,true><<<gDD, 256, 2*SM256>>>(xnH, xnL, wzT, bz, zb, zH, zL, MODEL_DIM, MODEL_DIM, nullptr, nullptr);
    hgemm<256,0,true,false><<<gDD, 256, 2*SM256>>>(xH, xL, wgT, bg, glin, nullptr, nullptr, MODEL_DIM, MODEL_DIM, nullptr, nullptr);
    // 3) decay net
    hgemm<128,1,false,true><<<dim3(INNER_DIM/128, NTOK/128), 256, 2*SM128>>>(zH, zL, md1T, mb1, nullptr, uH, uL, MODEL_DIM, INNER_DIM, nullptr, nullptr);
    hgemm<256,0,true,false><<<gDD, 256, 2*SM256>>>(uH, uL, md2T, mb2, tb, nullptr, nullptr, INNER_DIM, MODEL_DIM, nullptr, nullptr);
    hgemm<256,0,true,false><<<gDD, 256, 2*SM256>>>(kH, kL, mcwT, mcb, m2b, nullptr, nullptr, MODEL_DIM, MODEL_DIM, nullptr, nullptr);
    // 4) gamma + h_t (+ht planes)
    gamma_ht_kernel<<<(NTOK * MODEL_DIM) / (256 * 4), 256>>>(tb, m2b, zb, glin, x, gammab, htb, htH, htL);
    // 5) cumprod (second output)
    cumprod_local<<<dim3(NCHUNK, NBH), DH>>>(gammab, cum);
    cumprod_scan<<<(NBH * DH) / 256, 256>>>();
    cumprod_apply<<<dim3(NCHUNK, NBH), DH>>>(cum);
    // 6) attention
    hgemm<256,0,true,false><<<gDD, 256, 2*SM256>>>(htH, htL, awqT, abq, qab, nullptr, nullptr, MODEL_DIM, MODEL_DIM, nullptr, nullptr);
    hgemm<128,0,true,false><<<dim3(2*MODEL_DIM/128, 1), 256, 2*SM128>>>(memH, memL, awkvT, kvbias, kvb, nullptr, nullptr, MODEL_DIM, 2*MODEL_DIM, nullptr, nullptr);
    attn_kernel<<<dim3(SEQ / 64, NUM_HEADS, BATCH), 256, ATTN_SMEM>>>(qab, kvb, ctxH, ctxL);
    // 7) x_res = x + h_t + (ctx@awo + abo)
    hgemm<256,2,true,false><<<gDD, 256, 2*SM256>>>(ctxH, ctxL, awoT, abo, xresb, nullptr, nullptr, MODEL_DIM, MODEL_DIM, x, htb);
    // 8) FFN + residual -> first output
    rmsnorm_planes<<<NTOK, 256>>>(xresb, n2w, xn2H, xn2L);
    hgemm<256,1,false,true><<<gDF, 256, 2*SM256>>>(xn2H, xn2L, f1T, fb1, nullptr, a1H, a1L, MODEL_DIM, FFN_DIM, nullptr, nullptr);
    hgemm<256,3,true,false><<<gDD, 256, 2*SM256>>>(a1H, a1L, f2T, fb2, out, nullptr, nullptr, FFN_DIM, MODEL_DIM, xresb, nullptr);
}

// round 6
// speedup vs baseline: 7.5888x; 1.6814x over previous
#include <cuda_runtime.h>
#include <cuda_fp16.h>
#include <math.h>
#include <stdint.h>

#define MODEL_DIM 2048
#define INNER_DIM 512
#define NUM_HEADS 16
#define FFN_DIM   8192
#define MEM_TOKENS 64
#define BATCH 2
#define SEQ   2048
#define NTOK  (BATCH*SEQ)            // 4096
#define DH    (MODEL_DIM/NUM_HEADS)  // 128
#define EPSV  1e-6f

#define NCHUNK 32
#define CS     (SEQ/NCHUNK)          // 64
#define NBH    (BATCH*NUM_HEADS)     // 32

// ---------------- fp32 scratch -------------------------------------------------
__device__ float g_z    [NTOK*MODEL_DIM];
__device__ float g_glin [NTOK*MODEL_DIM];
__device__ float g_t    [NTOK*MODEL_DIM];
__device__ float g_m2   [NTOK*MODEL_DIM];
__device__ float g_gamma[NTOK*MODEL_DIM];
__device__ float g_ht   [NTOK*MODEL_DIM];
__device__ float g_qa   [NTOK*MODEL_DIM];
__device__ float g_kv   [BATCH*MEM_TOKENS*2*MODEL_DIM];   // [128, 4096] k|v
__device__ float g_xres [NTOK*MODEL_DIM];
__device__ float g_kvbias[2*MODEL_DIM];
__device__ float g_cp_tot [NBH*NCHUNK*DH];
__device__ float g_cp_pref[NBH*NCHUNK*DH];

// ---------------- fp16 activation planes (single) -------------------------------
__device__ __half g_xh  [NTOK*MODEL_DIM];
__device__ __half g_xnh [NTOK*MODEL_DIM];
__device__ __half g_zh  [NTOK*MODEL_DIM];
__device__ __half g_kh  [NTOK*MODEL_DIM];
__device__ __half g_uh  [NTOK*INNER_DIM];
__device__ __half g_hth [NTOK*MODEL_DIM];
__device__ __half g_memh[BATCH*MEM_TOKENS*MODEL_DIM];
__device__ __half g_ctxh[NTOK*MODEL_DIM];
__device__ __half g_xn2h[NTOK*MODEL_DIM];
__device__ __half g_a1h [NTOK*FFN_DIM];

// ---------------- fp16 transposed weights [Dout, K] ----------------------------
#define DD (MODEL_DIM*MODEL_DIM)
__device__ __half g_wk [DD], g_wz [DD], g_wg [DD], g_mcw[DD];
__device__ __half g_awq[DD], g_awo[DD];
__device__ __half g_awkv[2*MODEL_DIM*MODEL_DIM];          // rows 0..2047 = awk, 2048..4095 = awv
__device__ __half g_md1[MODEL_DIM*INNER_DIM];             // [512, 2048]
__device__ __half g_md2[INNER_DIM*MODEL_DIM];             // [2048, 512]
__device__ __half g_f1 [MODEL_DIM*FFN_DIM];               // [8192, 2048]
__device__ __half g_f2 [FFN_DIM*MODEL_DIM];               // [2048, 8192]

// ---------------- helpers -------------------------------------------------------
__device__ __forceinline__ uint32_t smem_to_u32(const void* p) {
    uint32_t a;
    asm("{ .reg .u64 t; cvta.to.shared.u64 t, %1; cvt.u32.u64 %0, t; }" : "=r"(a) : "l"(p));
    return a;
}
#define SMEM_SWIZZLE_128B(o) ((o) ^ (((o) >> 3) & 0x70))

__device__ __forceinline__ float gelu_f(float v) {
    float t = 0.7978845608028654f * (v + 0.044715f * v * v * v);
    return 0.5f * v * (1.0f + tanhf(t));
}
__device__ __forceinline__ float sigmoid_f(float v) { return 1.0f / (1.0f + expf(-v)); }

__device__ __forceinline__ void mma16816h(float* c, const uint32_t* a, const uint32_t* b) {
    asm volatile("mma.sync.aligned.m16n8k16.row.col.f32.f16.f16.f32 "
        "{%0,%1,%2,%3}, {%4,%5,%6,%7}, {%8,%9}, {%0,%1,%2,%3};"
        : "+f"(c[0]), "+f"(c[1]), "+f"(c[2]), "+f"(c[3])
        : "r"(a[0]), "r"(a[1]), "r"(a[2]), "r"(a[3]), "r"(b[0]), "r"(b[1]));
}
#define LDMATRIX_X4(r0, r1, r2, r3, addr) \
    asm volatile("ldmatrix.sync.aligned.m8n8.x4.shared.b16 {%0,%1,%2,%3}, [%4];" \
        : "=r"(r0), "=r"(r1), "=r"(r2), "=r"(r3) : "r"(addr))
#define CP_ASYNC_16(dst, src) \
    asm volatile("cp.async.cg.shared.global [%0], [%1], 16;" :: "r"(dst), "l"(src))
#define CP_COMMIT()  asm volatile("cp.async.commit_group;" ::: "memory")
#define CP_WAIT(n)   asm volatile("cp.async.wait_group %0;" :: "n"(n) : "memory")

// ---------------- weight transpose: W[K,D] -> T[D,K] fp16 -----------------------
__global__ void transpose_h(const float* __restrict__ W, __half* __restrict__ T,
                            int K, int D) {
    __shared__ float t[32][33];
    int d0 = blockIdx.x * 32, k0 = blockIdx.y * 32;
    int tx = threadIdx.x, ty = threadIdx.y;     // 32 x 8
    #pragma unroll
    for (int i = 0; i < 32; i += 8)
        t[ty + i][tx] = W[(size_t)(k0 + ty + i) * D + d0 + tx];
    __syncthreads();
    #pragma unroll
    for (int i = 0; i < 32; i += 8) {
        float v = t[tx][ty + i];
        T[(size_t)(d0 + ty + i) * K + k0 + tx] = __float2half_rn(v);
    }
}

// ---------------- fp32 -> fp16 --------------------------------------------------
__global__ void cvt_h(const float* __restrict__ src, __half* __restrict__ H) {
    size_t i = (size_t)(blockIdx.x * blockDim.x + threadIdx.x);
    float4 v = ((const float4*)src)[i];
    ((__half2*)H)[i * 2 + 0] = __floats2half2_rn(v.x, v.y);
    ((__half2*)H)[i * 2 + 1] = __floats2half2_rn(v.z, v.w);
}

__global__ void concat_bias(const float* __restrict__ a, const float* __restrict__ b) {
    int i = blockIdx.x * blockDim.x + threadIdx.x;
    g_kvbias[i] = (i < MODEL_DIM) ? a[i] : b[i - MODEL_DIM];
}

// ---------------- fp16 single-pass HMMA GEMM ------------------------------------
// C[M,Dout] = A[M,K] @ W[Dout,K]^T + bias.  Tile 128 x BN, BK=64, 8 warps, 3-stage.
// EPI: 0 none, 1 gelu, 2 +add1+add2, 3 +add1
template <int BN>
__device__ __forceinline__ void hg_issue(uint32_t base,
        const __half* Ab, const __half* Bb, int K, int k0, int tid) {
    #pragma unroll
    for (int i = 0; i < 4; i++) {           // A: 128 rows x 8 units = 1024
        int idx = tid + i * 256;
        int r = idx >> 3, u = idx & 7;
        uint32_t sw = SMEM_SWIZZLE_128B((uint32_t)(r * 128 + u * 16));
        CP_ASYNC_16(base + sw, Ab + (size_t)r * K + k0 + u * 8);
    }
    #pragma unroll
    for (int i = 0; i < (BN * 8) / 256; i++) {  // B: BN rows x 8 units
        int idx = tid + i * 256;
        int r = idx >> 3, u = idx & 7;
        uint32_t sw = SMEM_SWIZZLE_128B((uint32_t)(r * 128 + u * 16));
        CP_ASYNC_16(base + 16384 + sw, Bb + (size_t)r * K + k0 + u * 8);
    }
    CP_COMMIT();
}

template <int BN, int EPI, bool WF32, bool WPL>
__global__ void __launch_bounds__(256, 1)
hgemm(const __half* __restrict__ A, const __half* __restrict__ Bp,
      const float* __restrict__ bias,
      float* __restrict__ C, __half* __restrict__ PH,
      int K, int Dout, const float* __restrict__ add1, const float* __restrict__ add2) {
    constexpr int NJ = BN / 32;
    constexpr int STAGE = 16384 + BN * 128;
    extern __shared__ __align__(1024) char sm[];
    uint32_t sb = smem_to_u32(sm);
    int tid = threadIdx.x;
    int wid = tid >> 5, lane = tid & 31;
    int wm = wid & 1, wn = wid >> 1;       // 2 (M) x 4 (N) warps

    const __half* Ab = A  + (size_t)blockIdx.y * 128 * K;
    const __half* Bb = Bp + (size_t)blockIdx.x * BN * K;

    float acc[4][NJ][4];
    #pragma unroll
    for (int i = 0; i < 4; i++)
        #pragma unroll
        for (int j = 0; j < NJ; j++)
            #pragma unroll
            for (int q = 0; q < 4; q++) acc[i][j][q] = 0.0f;

    int NS = K >> 6;   // K >= 512 -> NS >= 8 (3-stage prologue safe)
    hg_issue<BN>(sb,             Ab, Bb, K, 0,   tid);
    hg_issue<BN>(sb + STAGE,     Ab, Bb, K, 64,  tid);
    hg_issue<BN>(sb + 2 * STAGE, Ab, Bb, K, 128, tid);

    uint32_t st = 0;  // stage index s % 3
    for (int s = 0; s < NS; s++) {
        CP_WAIT(2);
        __syncthreads();
        uint32_t aA = sb + st * STAGE;
        uint32_t bB = aA + 16384;
        #pragma unroll
        for (int ks = 0; ks < 4; ks++) {
            uint32_t af[4][4], bf[NJ][2];
            #pragma unroll
            for (int i = 0; i < 4; i++) {
                int row = wm * 64 + i * 16 + (lane & 15);
                int kb = ks * 32 + (lane >> 4) * 16;
                uint32_t sw = SMEM_SWIZZLE_128B((uint32_t)(row * 128 + kb));
                LDMATRIX_X4(af[i][0], af[i][1], af[i][2], af[i][3], aA + sw);
            }
            #pragma unroll
            for (int jp = 0; jp < NJ / 2; jp++) {
                int n = wn * (BN / 4) + jp * 16 + (lane >> 4) * 8 + (lane & 7);
                int kb = ks * 32 + ((lane >> 3) & 1) * 16;
                uint32_t sw = SMEM_SWIZZLE_128B((uint32_t)(n * 128 + kb));
                LDMATRIX_X4(bf[2*jp][0], bf[2*jp][1], bf[2*jp+1][0], bf[2*jp+1][1], bB + sw);
            }
            #pragma unroll
            for (int i = 0; i < 4; i++)
                #pragma unroll
                for (int j = 0; j < NJ; j++) mma16816h(acc[i][j], af[i], bf[j]);
        }
        __syncthreads();
        if (s + 3 < NS) hg_issue<BN>(sb + st * STAGE, Ab, Bb, K, (s + 3) * 64, tid);
        else CP_COMMIT();   // keep group count aligned for CP_WAIT(2)
        st = (st == 2) ? 0 : st + 1;
    }

    // ---- epilogue
    int gr = lane >> 2;        // 0..7
    int gc = (lane & 3) * 2;   // 0,2,4,6
    #pragma unroll
    for (int i = 0; i < 4; i++) {
        int row0 = blockIdx.y * 128 + wm * 64 + i * 16 + gr;
        #pragma unroll
        for (int j = 0; j < NJ; j++) {
            int col = blockIdx.x * BN + wn * (BN / 4) + j * 8 + gc;
            float2 bv = *(const float2*)(bias + col);
            #pragma unroll
            for (int half = 0; half < 2; half++) {
                int row = row0 + half * 8;
                size_t idx = (size_t)row * Dout + col;
                float2 o;
                o.x = acc[i][j][half * 2 + 0] + bv.x;
                o.y = acc[i][j][half * 2 + 1] + bv.y;
                if (EPI == 1) { o.x = gelu_f(o.x); o.y = gelu_f(o.y); }
                if (EPI == 2) {
                    float2 a1 = *(const float2*)(add1 + idx);
                    float2 a2 = *(const float2*)(add2 + idx);
                    o.x += a1.x + a2.x; o.y += a1.y + a2.y;
                }
                if (EPI == 3) {
                    float2 a1 = *(const float2*)(add1 + idx);
                    o.x += a1.x; o.y += a1.y;
                }
                if (WF32) *(float2*)(C + idx) = o;
                if (WPL)  *(__half2*)(PH + idx) = __floats2half2_rn(o.x, o.y);
            }
        }
    }
}

// ---------------- RMSNorm -> fp16 -----------------------------------------------
__global__ void rmsnorm_h(const float* __restrict__ x,
                          const float* __restrict__ w,
                          __half* __restrict__ H) {
    int row = blockIdx.x;
    int t = threadIdx.x;  // 256
    const float4* xr = (const float4*)(x + (size_t)row * MODEL_DIM);
    float4 v0 = xr[t];
    float4 v1 = xr[t + 256];
    float s = v0.x*v0.x + v0.y*v0.y + v0.z*v0.z + v0.w*v0.w
            + v1.x*v1.x + v1.y*v1.y + v1.z*v1.z + v1.w*v1.w;
    #pragma unroll
    for (int o = 16; o > 0; o >>= 1) s += __shfl_xor_sync(0xffffffffu, s, o);
    __shared__ float red[8];
    if ((t & 31) == 0) red[t >> 5] = s;
    __syncthreads();
    float tot = red[0]+red[1]+red[2]+red[3]+red[4]+red[5]+red[6]+red[7];
    float inv = 1.0f / (sqrtf(tot / (float)MODEL_DIM) + EPSV);
    const float4* wr = (const float4*)w;
    float4 w0 = wr[t], w1 = wr[t + 256];
    __half2* Hr = (__half2*)(H + (size_t)row * MODEL_DIM);
    Hr[t*2]       = __floats2half2_rn(w0.x*v0.x*inv, w0.y*v0.y*inv);
    Hr[t*2+1]     = __floats2half2_rn(w0.z*v0.z*inv, w0.w*v0.w*inv);
    Hr[512+t*2]   = __floats2half2_rn(w1.x*v1.x*inv, w1.y*v1.y*inv);
    Hr[512+t*2+1] = __floats2half2_rn(w1.z*v1.z*inv, w1.w*v1.w*inv);
}

// ---------------- gamma / h_t elementwise (+ ht fp16) ----------------------------
__global__ void gamma_ht_kernel(const float* __restrict__ t,
                                const float* __restrict__ m2,
                                const float* __restrict__ z,
                                const float* __restrict__ glin,
                                const float* __restrict__ x,
                                float* __restrict__ gamma,
                                float* __restrict__ ht,
                                __half* __restrict__ hth) {
    size_t i = (size_t)(blockIdx.x * blockDim.x + threadIdx.x);
    float4 tv = ((const float4*)t)[i];
    float4 mv = ((const float4*)m2)[i];
    float4 zv = ((const float4*)z)[i];
    float4 gv = ((const float4*)glin)[i];
    float4 xv = ((const float4*)x)[i];
    float4 gm, h;
    gm.x = sigmoid_f(tv.x + mv.x); gm.y = sigmoid_f(tv.y + mv.y);
    gm.z = sigmoid_f(tv.z + mv.z); gm.w = sigmoid_f(tv.w + mv.w);
    h.x = zv.x * sigmoid_f(gv.x) + gm.x * xv.x;
    h.y = zv.y * sigmoid_f(gv.y) + gm.y * xv.y;
    h.z = zv.z * sigmoid_f(gv.z) + gm.z * xv.z;
    h.w = zv.w * sigmoid_f(gv.w) + gm.w * xv.w;
    ((float4*)gamma)[i] = gm;
    ((float4*)ht)[i] = h;
    ((__half2*)hth)[i*2]   = __floats2half2_rn(h.x, h.y);
    ((__half2*)hth)[i*2+1] = __floats2half2_rn(h.z, h.w);
}

// ---------------- cumprod ---------------------------------------------------------
__global__ void cumprod_local(const float* __restrict__ gamma, float* __restrict__ outp) {
    int c = blockIdx.x, bh = blockIdx.y, d2 = threadIdx.x;
    size_t base = (size_t)bh * SEQ * DH + (size_t)c * CS * DH + d2;
    float p = 1.0f;
    for (int i = 0; i < CS; i++) {
        p *= gamma[base + (size_t)i * DH];
        outp[base + (size_t)i * DH] = p;
    }
    g_cp_tot[(bh * NCHUNK + c) * DH + d2] = p;
}
__global__ void cumprod_scan() {
    int lane = blockIdx.x * blockDim.x + threadIdx.x;
    int bh = lane / DH, d2 = lane % DH;
    float r = 1.0f;
    for (int c = 0; c < NCHUNK; c++) {
        int idx = (bh * NCHUNK + c) * DH + d2;
        g_cp_pref[idx] = r;
        r *= g_cp_tot[idx];
    }
}
__global__ void cumprod_apply(float* __restrict__ outp) {
    int c = blockIdx.x, bh = blockIdx.y, d2 = threadIdx.x;
    if (c == 0) return;
    float pref = g_cp_pref[(bh * NCHUNK + c) * DH + d2];
    size_t base = (size_t)bh * SEQ * DH + (size_t)c * CS * DH + d2;
    for (int i = 0; i < CS; i++) outp[base + (size_t)i * DH] *= pref;
}

// ---------------- attention over 64 memory tokens (out -> fp16) -------------------
#define ATTN_SMEM ((64*128 + 128*68 + 64*128 + 64*66) * 4)
__global__ void attn_kernel(const float* __restrict__ qa,
                            const float* __restrict__ kv,
                            __half* __restrict__ ctxh) {
    extern __shared__ float smf[];
    float* qs  = smf;
    float* kst = qs + 64 * 128;
    float* vs  = kst + 128 * 68;
    float* sc  = vs + 64 * 128;
    int st = blockIdx.x, h = blockIdx.y, b = blockIdx.z;
    int s0 = st * 64;
    int tid = threadIdx.x;

    for (int l = tid; l < 64 * 32; l += 256) {
        int r = l >> 5, c4 = (l & 31) * 4;
        float4 v = *(const float4*)(qa + (size_t)(b * SEQ + s0 + r) * MODEL_DIM + h * 128 + c4);
        *(float4*)&qs[r * 128 + c4] = v;
    }
    for (int l = tid; l < 64 * 32; l += 256) {
        int m = l >> 5, c4 = (l & 31) * 4;
        float4 v = *(const float4*)(kv + (size_t)(b * MEM_TOKENS + m) * (2 * MODEL_DIM) + h * 128 + c4);
        kst[(c4 + 0) * 68 + m] = v.x; kst[(c4 + 1) * 68 + m] = v.y;
        kst[(c4 + 2) * 68 + m] = v.z; kst[(c4 + 3) * 68 + m] = v.w;
    }
    for (int l = tid; l < 64 * 32; l += 256) {
        int m = l >> 5, c4 = (l & 31) * 4;
        float4 v = *(const float4*)(kv + (size_t)(b * MEM_TOKENS + m) * (2 * MODEL_DIM)
                                    + MODEL_DIM + h * 128 + c4);
        *(float4*)&vs[m * 128 + c4] = v;
    }
    __syncthreads();

    int tx = tid & 15, ty = tid >> 4;
    float acc[4][4];
    #pragma unroll
    for (int i = 0; i < 4; i++)
        #pragma unroll
        for (int j = 0; j < 4; j++) acc[i][j] = 0.0f;
    #pragma unroll 4
    for (int d = 0; d < 128; d++) {
        float4 bv = *(const float4*)&kst[d * 68 + tx * 4];
        float a0 = qs[(ty * 4 + 0) * 128 + d];
        float a1 = qs[(ty * 4 + 1) * 128 + d];
        float a2 = qs[(ty * 4 + 2) * 128 + d];
        float a3 = qs[(ty * 4 + 3) * 128 + d];
        acc[0][0] += a0 * bv.x; acc[0][1] += a0 * bv.y; acc[0][2] += a0 * bv.z; acc[0][3] += a0 * bv.w;
        acc[1][0] += a1 * bv.x; acc[1][1] += a1 * bv.y; acc[1][2] += a1 * bv.z; acc[1][3] += a1 * bv.w;
        acc[2][0] += a2 * bv.x; acc[2][1] += a2 * bv.y; acc[2][2] += a2 * bv.z; acc[2][3] += a2 * bv.w;
        acc[3][0] += a3 * bv.x; acc[3][1] += a3 * bv.y; acc[3][2] += a3 * bv.z; acc[3][3] += a3 * bv.w;
    }
    const float scale = 0.08838834764831845f;
    #pragma unroll
    for (int i = 0; i < 4; i++)
        #pragma unroll
        for (int j = 0; j < 4; j++)
            sc[(ty * 4 + i) * 66 + tx * 4 + j] = acc[i][j] * scale;
    __syncthreads();

    if (tid < 64) {
        float* row = &sc[tid * 66];
        float mx = -1e30f;
        for (int m = 0; m < 64; m++) mx = fmaxf(mx, row[m]);
        float s = 0.0f;
        for (int m = 0; m < 64; m++) { float e = expf(row[m] - mx); row[m] = e; s += e; }
        float inv = 1.0f / s;
        for (int m = 0; m < 64; m++) row[m] *= inv;
    }
    __syncthreads();

    float o[4][8];
    #pragma unroll
    for (int i = 0; i < 4; i++)
        #pragma unroll
        for (int j = 0; j < 8; j++) o[i][j] = 0.0f;
    #pragma unroll 4
    for (int m = 0; m < 64; m++) {
        float p0 = sc[(ty * 4 + 0) * 66 + m];
        float p1 = sc[(ty * 4 + 1) * 66 + m];
        float p2 = sc[(ty * 4 + 2) * 66 + m];
        float p3 = sc[(ty * 4 + 3) * 66 + m];
        float4 v0 = *(const float4*)&vs[m * 128 + tx * 8];
        float4 v1 = *(const float4*)&vs[m * 128 + tx * 8 + 4];
        float vv[8] = {v0.x, v0.y, v0.z, v0.w, v1.x, v1.y, v1.z, v1.w};
        #pragma unroll
        for (int j = 0; j < 8; j++) {
            o[0][j] += p0 * vv[j]; o[1][j] += p1 * vv[j];
            o[2][j] += p2 * vv[j]; o[3][j] += p3 * vv[j];
        }
    }
    #pragma unroll
    for (int i = 0; i < 4; i++) {
        size_t base = (size_t)(b * SEQ + s0 + ty * 4 + i) * MODEL_DIM + h * 128 + tx * 8;
        #pragma unroll
        for (int jp = 0; jp < 4; jp++)
            *(__half2*)(ctxh + base + jp * 2) = __floats2half2_rn(o[i][jp * 2], o[i][jp * 2 + 1]);
    }
}

// ---------------- host launcher -----------------------------------------------------
extern "C" void kernel_launch(void* const* d_in, const int* in_sizes, int n_in,
                              void* d_out, int out_size) {
    bool sig = (in_sizes[3] == MODEL_DIM);
    const float *x, *memory, *wk, *bk, *wz, *bz, *wg, *bg, *n1w, *n2w;
    const float *md1, *mb1, *md2, *mb2, *mcw, *mcb;
    const float *awq, *abq, *awk, *abk, *awv, *abv, *awo, *abo;
    const float *f1, *fb1, *f2, *fb2;
    #define IN(i) ((const float*)d_in[(i)])
    if (sig) {
        x = IN(0);  memory = IN(1);
        wk = IN(4);  bk = IN(5);  wz = IN(8);  bz = IN(9);  wg = IN(10); bg = IN(11);
        n1w = IN(12); n2w = IN(13);
        md1 = IN(14); mb1 = IN(15); md2 = IN(16); mb2 = IN(17); mcw = IN(18); mcb = IN(19);
        awq = IN(20); abq = IN(21); awk = IN(22); abk = IN(23); awv = IN(24); abv = IN(25);
        awo = IN(26); abo = IN(27);
        f1 = IN(28); fb1 = IN(29); f2 = IN(30); fb2 = IN(31);
    } else {
        x = IN(0);  memory = IN(1);
        wk = IN(3);  wz = IN(5);  wg = IN(6);
        md1 = IN(7); md2 = IN(8); mcw = IN(9);
        awq = IN(10); awk = IN(11); awv = IN(12); awo = IN(13);
        f1 = IN(14); f2 = IN(15);
        bk = IN(17); bz = IN(19); bg = IN(20);
        mb1 = IN(21); mb2 = IN(22); mcb = IN(23);
        abq = IN(24); abk = IN(25); abv = IN(26); abo = IN(27);
        fb1 = IN(28); fb2 = IN(29);
        n1w = IN(30); n2w = IN(31);
    }
    #undef IN

    float *zb, *glin, *tb, *m2b, *gammab, *htb, *qab, *kvb, *xresb, *kvbias;
    cudaGetSymbolAddress((void**)&zb,    g_z);
    cudaGetSymbolAddress((void**)&glin,  g_glin);
    cudaGetSymbolAddress((void**)&tb,    g_t);
    cudaGetSymbolAddress((void**)&m2b,   g_m2);
    cudaGetSymbolAddress((void**)&gammab,g_gamma);
    cudaGetSymbolAddress((void**)&htb,   g_ht);
    cudaGetSymbolAddress((void**)&qab,   g_qa);
    cudaGetSymbolAddress((void**)&kvb,   g_kv);
    cudaGetSymbolAddress((void**)&xresb, g_xres);
    cudaGetSymbolAddress((void**)&kvbias,g_kvbias);

    __half *xh,*xnh,*zh,*kh,*uh,*hth,*memh,*ctxh,*xn2h,*a1h;
    cudaGetSymbolAddress((void**)&xh,  g_xh);
    cudaGetSymbolAddress((void**)&xnh, g_xnh);
    cudaGetSymbolAddress((void**)&zh,  g_zh);
    cudaGetSymbolAddress((void**)&kh,  g_kh);
    cudaGetSymbolAddress((void**)&uh,  g_uh);
    cudaGetSymbolAddress((void**)&hth, g_hth);
    cudaGetSymbolAddress((void**)&memh,g_memh);
    cudaGetSymbolAddress((void**)&ctxh,g_ctxh);
    cudaGetSymbolAddress((void**)&xn2h,g_xn2h);
    cudaGetSymbolAddress((void**)&a1h, g_a1h);

    __half *wkT,*wzT,*wgT,*mcwT,*awqT,*awoT,*awkvT,*md1T,*md2T,*f1T,*f2T;
    cudaGetSymbolAddress((void**)&wkT,  g_wk);
    cudaGetSymbolAddress((void**)&wzT,  g_wz);
    cudaGetSymbolAddress((void**)&wgT,  g_wg);
    cudaGetSymbolAddress((void**)&mcwT, g_mcw);
    cudaGetSymbolAddress((void**)&awqT, g_awq);
    cudaGetSymbolAddress((void**)&awoT, g_awo);
    cudaGetSymbolAddress((void**)&awkvT,g_awkv);
    cudaGetSymbolAddress((void**)&md1T, g_md1);
    cudaGetSymbolAddress((void**)&md2T, g_md2);
    cudaGetSymbolAddress((void**)&f1T,  g_f1);
    cudaGetSymbolAddress((void**)&f2T,  g_f2);

    float* out = (float*)d_out;
    float* cum = out + (size_t)NTOK * MODEL_DIM;

    const int SM256 = 16384 + 256 * 128;   // 49152 per stage
    const int SM128 = 16384 + 128 * 128;   // 32768 per stage
    cudaFuncSetAttribute((const void*)hgemm<256,0,false,true>,  cudaFuncAttributeMaxDynamicSharedMemorySize, 3*SM256);
    cudaFuncSetAttribute((const void*)hgemm<256,0,true,true>,   cudaFuncAttributeMaxDynamicSharedMemorySize, 3*SM256);
    cudaFuncSetAttribute((const void*)hgemm<256,0,true,false>,  cudaFuncAttributeMaxDynamicSharedMemorySize, 3*SM256);
    cudaFuncSetAttribute((const void*)hgemm<256,1,false,true>,  cudaFuncAttributeMaxDynamicSharedMemorySize, 3*SM256);
    cudaFuncSetAttribute((const void*)hgemm<256,2,true,false>,  cudaFuncAttributeMaxDynamicSharedMemorySize, 3*SM256);
    cudaFuncSetAttribute((const void*)hgemm<256,3,true,false>,  cudaFuncAttributeMaxDynamicSharedMemorySize, 3*SM256);
    cudaFuncSetAttribute((const void*)hgemm<128,1,false,true>,  cudaFuncAttributeMaxDynamicSharedMemorySize, 3*SM128);
    cudaFuncSetAttribute((const void*)hgemm<128,0,true,false>,  cudaFuncAttributeMaxDynamicSharedMemorySize, 3*SM128);
    cudaFuncSetAttribute(attn_kernel, cudaFuncAttributeMaxDynamicSharedMemorySize, ATTN_SMEM);

    // ---- weight transposes (fp16 single plane)
    dim3 tb8(32, 8);
    dim3 gT(MODEL_DIM / 32, MODEL_DIM / 32);
    transpose_h<<<gT, tb8>>>(wk,  wkT,  MODEL_DIM, MODEL_DIM);
    transpose_h<<<gT, tb8>>>(wz,  wzT,  MODEL_DIM, MODEL_DIM);
    transpose_h<<<gT, tb8>>>(wg,  wgT,  MODEL_DIM, MODEL_DIM);
    transpose_h<<<gT, tb8>>>(mcw, mcwT, MODEL_DIM, MODEL_DIM);
    transpose_h<<<gT, tb8>>>(awq, awqT, MODEL_DIM, MODEL_DIM);
    transpose_h<<<gT, tb8>>>(awo, awoT, MODEL_DIM, MODEL_DIM);
    transpose_h<<<gT, tb8>>>(awk, awkvT,                               MODEL_DIM, MODEL_DIM);
    transpose_h<<<gT, tb8>>>(awv, awkvT + (size_t)MODEL_DIM*MODEL_DIM, MODEL_DIM, MODEL_DIM);
    transpose_h<<<dim3(INNER_DIM / 32, MODEL_DIM / 32), tb8>>>(md1, md1T, MODEL_DIM, INNER_DIM);
    transpose_h<<<dim3(MODEL_DIM / 32, INNER_DIM / 32), tb8>>>(md2, md2T, INNER_DIM, MODEL_DIM);
    transpose_h<<<dim3(FFN_DIM / 32,  MODEL_DIM / 32), tb8>>>(f1, f1T, MODEL_DIM, FFN_DIM);
    transpose_h<<<dim3(MODEL_DIM / 32, FFN_DIM / 32),  tb8>>>(f2, f2T, FFN_DIM, MODEL_DIM);
    concat_bias<<<(2 * MODEL_DIM) / 256, 256>>>(abk, abv);

    // ---- fp16 copies of raw inputs
    cvt_h<<<(NTOK * MODEL_DIM / 4) / 256, 256>>>(x, xh);
    cvt_h<<<(BATCH * MEM_TOKENS * MODEL_DIM / 4) / 64, 64>>>(memory, memh);

    dim3 gDD(MODEL_DIM / 256, NTOK / 128);   // (8, 32)
    dim3 gDF(FFN_DIM / 256,  NTOK / 128);    // (32, 32)

    // 1) xn = rmsnorm(x, n1w) -> fp16
    rmsnorm_h<<<NTOK, 256>>>(x, n1w, xnh);
    // 2) projections
    hgemm<256,0,false,true><<<gDD, 256, 3*SM256>>>(xnh, wkT, bk, nullptr, kh, MODEL_DIM, MODEL_DIM, nullptr, nullptr);
    hgemm<256,0,true,true><<<gDD, 256, 3*SM256>>>(xnh, wzT, bz, zb, zh, MODEL_DIM, MODEL_DIM, nullptr, nullptr);
    hgemm<256,0,true,false><<<gDD, 256, 3*SM256>>>(xh, wgT, bg, glin, nullptr, MODEL_DIM, MODEL_DIM, nullptr, nullptr);
    // 3) decay net
    hgemm<128,1,false,true><<<dim3(INNER_DIM/128, NTOK/128), 256, 3*SM128>>>(zh, md1T, mb1, nullptr, uh, MODEL_DIM, INNER_DIM, nullptr, nullptr);
    hgemm<256,0,true,false><<<gDD, 256, 3*SM256>>>(uh, md2T, mb2, tb, nullptr, INNER_DIM, MODEL_DIM, nullptr, nullptr);
    hgemm<256,0,true,false><<<gDD, 256, 3*SM256>>>(kh, mcwT, mcb, m2b, nullptr, MODEL_DIM, MODEL_DIM, nullptr, nullptr);
    // 4) gamma + h_t (+ht fp16)
    gamma_ht_kernel<<<(NTOK * MODEL_DIM) / (256 * 4), 256>>>(tb, m2b, zb, glin, x, gammab, htb, hth);
    // 5) cumprod (second output)
    cumprod_local<<<dim3(NCHUNK, NBH), DH>>>(gammab, cum);
    cumprod_scan<<<(NBH * DH) / 256, 256>>>();
    cumprod_apply<<<dim3(NCHUNK, NBH), DH>>>(cum);
    // 6) attention
    hgemm<256,0,true,false><<<gDD, 256, 3*SM256>>>(hth, awqT, abq, qab, nullptr, MODEL_DIM, MODEL_DIM, nullptr, nullptr);
    hgemm<128,0,true,false><<<dim3(2*MODEL_DIM/128, 1), 256, 3*SM128>>>(memh, awkvT, kvbias, kvb, nullptr, MODEL_DIM, 2*MODEL_DIM, nullptr, nullptr);
    attn_kernel<<<dim3(SEQ / 64, NUM_HEADS, BATCH), 256, ATTN_SMEM>>>(qab, kvb, ctxh);
    // 7) x_res = x + h_t + (ctx@awo + abo)
    hgemm<256,2,true,false><<<gDD, 256, 3*SM256>>>(ctxh, awoT, abo, xresb, nullptr, MODEL_DIM, MODEL_DIM, x, htb);
    // 8) FFN + residual -> first output
    rmsnorm_h<<<NTOK, 256>>>(xresb, n2w, xn2h);
    hgemm<256,1,false,true><<<gDF, 256, 3*SM256>>>(xn2h, f1T, fb1, nullptr, a1h, MODEL_DIM, FFN_DIM, nullptr, nullptr);
    hgemm<256,3,true,false><<<gDD, 256, 3*SM256>>>(a1h, f2T, fb2, out, nullptr, FFN_DIM, MODEL_DIM, xresb, nullptr);
}

// round 7
// speedup vs baseline: 8.0470x; 1.0604x over previous
#include <cuda_runtime.h>
#include <cuda_fp16.h>
#include <math.h>
#include <stdint.h>

#define MODEL_DIM 2048
#define INNER_DIM 512
#define NUM_HEADS 16
#define FFN_DIM   8192
#define MEM_TOKENS 64
#define BATCH 2
#define SEQ   2048
#define NTOK  (BATCH*SEQ)            // 4096
#define DH    (MODEL_DIM/NUM_HEADS)  // 128
#define EPSV  1e-6f

#define NCHUNK 32
#define CS     (SEQ/NCHUNK)          // 64
#define NBH    (BATCH*NUM_HEADS)     // 32

// ---------------- fp32 scratch -------------------------------------------------
__device__ float g_z    [NTOK*MODEL_DIM];
__device__ float g_glin [NTOK*MODEL_DIM];
__device__ float g_t    [NTOK*MODEL_DIM];
__device__ float g_m2   [NTOK*MODEL_DIM];
__device__ float g_gamma[NTOK*MODEL_DIM];
__device__ float g_ht   [NTOK*MODEL_DIM];
__device__ float g_xres [NTOK*MODEL_DIM];
__device__ float g_kvbias[2*MODEL_DIM];
__device__ float g_cp_tot [NBH*NCHUNK*DH];
__device__ float g_cp_pref[NBH*NCHUNK*DH];

// ---------------- fp16 activations ----------------------------------------------
__device__ __half g_xh  [NTOK*MODEL_DIM];
__device__ __half g_xnh [NTOK*MODEL_DIM];
__device__ __half g_zh  [NTOK*MODEL_DIM];
__device__ __half g_kh  [NTOK*MODEL_DIM];
__device__ __half g_uh  [NTOK*INNER_DIM];
__device__ __half g_hth [NTOK*MODEL_DIM];
__device__ __half g_memh[BATCH*MEM_TOKENS*MODEL_DIM];
__device__ __half g_qah [NTOK*MODEL_DIM];
__device__ __half g_kvh [BATCH*MEM_TOKENS*2*MODEL_DIM];   // [128, 4096] k|v
__device__ __half g_ctxh[NTOK*MODEL_DIM];
__device__ __half g_xn2h[NTOK*MODEL_DIM];
__device__ __half g_a1h [NTOK*FFN_DIM];

// ---------------- fp16 transposed weights [Dout, K] ----------------------------
#define DD (MODEL_DIM*MODEL_DIM)
__device__ __half g_wk [DD], g_wz [DD], g_wg [DD], g_mcw[DD];
__device__ __half g_awq[DD], g_awo[DD];
__device__ __half g_awkv[2*MODEL_DIM*MODEL_DIM];
__device__ __half g_md1[MODEL_DIM*INNER_DIM];
__device__ __half g_md2[INNER_DIM*MODEL_DIM];
__device__ __half g_f1 [MODEL_DIM*FFN_DIM];
__device__ __half g_f2 [FFN_DIM*MODEL_DIM];

// ---------------- helpers -------------------------------------------------------
__device__ __forceinline__ uint32_t smem_to_u32(const void* p) {
    uint32_t a;
    asm("{ .reg .u64 t; cvta.to.shared.u64 t, %1; cvt.u32.u64 %0, t; }" : "=r"(a) : "l"(p));
    return a;
}
#define SMEM_SWIZZLE_128B(o) ((o) ^ (((o) >> 3) & 0x70))

__device__ __forceinline__ float gelu_f(float v) {
    float t = 0.7978845608028654f * (v + 0.044715f * v * v * v);
    return 0.5f * v * (1.0f + tanhf(t));
}
__device__ __forceinline__ float sigmoid_f(float v) { return 1.0f / (1.0f + expf(-v)); }

__device__ __forceinline__ void mma16816h(float* c, const uint32_t* a, const uint32_t* b) {
    asm volatile("mma.sync.aligned.m16n8k16.row.col.f32.f16.f16.f32 "
        "{%0,%1,%2,%3}, {%4,%5,%6,%7}, {%8,%9}, {%0,%1,%2,%3};"
        : "+f"(c[0]), "+f"(c[1]), "+f"(c[2]), "+f"(c[3])
        : "r"(a[0]), "r"(a[1]), "r"(a[2]), "r"(a[3]), "r"(b[0]), "r"(b[1]));
}
#define LDMATRIX_X4(r0, r1, r2, r3, addr) \
    asm volatile("ldmatrix.sync.aligned.m8n8.x4.shared.b16 {%0,%1,%2,%3}, [%4];" \
        : "=r"(r0), "=r"(r1), "=r"(r2), "=r"(r3) : "r"(addr))
#define CP_ASYNC_16(dst, src) \
    asm volatile("cp.async.cg.shared.global [%0], [%1], 16;" :: "r"(dst), "l"(src))
#define CP_COMMIT()  asm volatile("cp.async.commit_group;" ::: "memory")
#define CP_WAIT(n)   asm volatile("cp.async.wait_group %0;" :: "n"(n) : "memory")

// ---------------- weight transpose: W[K,D] -> T[D,K] fp16, half2 stores ---------
__global__ void transpose_h2(const float* __restrict__ W, __half* __restrict__ T,
                             int K, int D) {
    __shared__ float t[64][33];
    int d0 = blockIdx.x * 32, k0 = blockIdx.y * 64;
    int tx = threadIdx.x, ty = threadIdx.y;     // 32 x 8
    #pragma unroll
    for (int i = 0; i < 64; i += 8)
        t[ty + i][tx] = W[(size_t)(k0 + ty + i) * D + d0 + tx];
    __syncthreads();
    #pragma unroll
    for (int i = 0; i < 32; i += 8) {
        int d = d0 + ty + i;
        float v0 = t[tx * 2][ty + i];
        float v1 = t[tx * 2 + 1][ty + i];
        *(__half2*)(T + (size_t)d * K + k0 + tx * 2) = __floats2half2_rn(v0, v1);
    }
}

// ---------------- fp32 -> fp16 --------------------------------------------------
__global__ void cvt_h(const float* __restrict__ src, __half* __restrict__ H) {
    size_t i = (size_t)(blockIdx.x * blockDim.x + threadIdx.x);
    float4 v = ((const float4*)src)[i];
    ((__half2*)H)[i * 2 + 0] = __floats2half2_rn(v.x, v.y);
    ((__half2*)H)[i * 2 + 1] = __floats2half2_rn(v.z, v.w);
}

__global__ void concat_bias(const float* __restrict__ a, const float* __restrict__ b) {
    int i = blockIdx.x * blockDim.x + threadIdx.x;
    g_kvbias[i] = (i < MODEL_DIM) ? a[i] : b[i - MODEL_DIM];
}

// ---------------- fp16 single-pass HMMA GEMM, 4-stage single-barrier -------------
// C[M,Dout] = A[M,K] @ W[Dout,K]^T + bias.  Tile 128 x BN, BK=64, 8 warps.
// EPI: 0 none, 1 gelu, 2 +add1+add2, 3 +add1
template <int BN>
__device__ __forceinline__ void hg_issue(uint32_t base,
        const __half* Ab, const __half* Bb, int K, int k0, int tid) {
    #pragma unroll
    for (int i = 0; i < 4; i++) {           // A: 128 rows x 8 units
        int idx = tid + i * 256;
        int r = idx >> 3, u = idx & 7;
        uint32_t sw = SMEM_SWIZZLE_128B((uint32_t)(r * 128 + u * 16));
        CP_ASYNC_16(base + sw, Ab + (size_t)r * K + k0 + u * 8);
    }
    #pragma unroll
    for (int i = 0; i < (BN * 8) / 256; i++) {  // B: BN rows x 8 units
        int idx = tid + i * 256;
        int r = idx >> 3, u = idx & 7;
        uint32_t sw = SMEM_SWIZZLE_128B((uint32_t)(r * 128 + u * 16));
        CP_ASYNC_16(base + 16384 + sw, Bb + (size_t)r * K + k0 + u * 8);
    }
    CP_COMMIT();
}

template <int BN, int EPI, bool WF32, bool WPL>
__global__ void __launch_bounds__(256, 1)
hgemm(const __half* __restrict__ A, const __half* __restrict__ Bp,
      const float* __restrict__ bias,
      float* __restrict__ C, __half* __restrict__ PH,
      int K, int Dout, const float* __restrict__ add1, const float* __restrict__ add2) {
    constexpr int NJ = BN / 32;
    constexpr int STAGE = 16384 + BN * 128;
    extern __shared__ __align__(1024) char sm[];
    uint32_t sb = smem_to_u32(sm);
    int tid = threadIdx.x;
    int wid = tid >> 5, lane = tid & 31;
    int wm = wid & 1, wn = wid >> 1;       // 2 (M) x 4 (N) warps

    const __half* Ab = A  + (size_t)blockIdx.y * 128 * K;
    const __half* Bb = Bp + (size_t)blockIdx.x * BN * K;

    float acc[4][NJ][4];
    #pragma unroll
    for (int i = 0; i < 4; i++)
        #pragma unroll
        for (int j = 0; j < NJ; j++)
            #pragma unroll
            for (int q = 0; q < 4; q++) acc[i][j][q] = 0.0f;

    int NS = K >> 6;   // >= 8 for all shapes used
    hg_issue<BN>(sb + 0u * STAGE, Ab, Bb, K, 0,   tid);
    hg_issue<BN>(sb + 1u * STAGE, Ab, Bb, K, 64,  tid);
    hg_issue<BN>(sb + 2u * STAGE, Ab, Bb, K, 128, tid);

    for (int s = 0; s < NS; s++) {
        CP_WAIT(2);
        __syncthreads();
        // issue s+3 into buffer (s+3)&3 == (s-1)&3, consumed at iteration s-1
        if (s + 3 < NS) hg_issue<BN>(sb + (uint32_t)((s + 3) & 3) * STAGE, Ab, Bb, K, (s + 3) * 64, tid);
        else CP_COMMIT();  // keep group count aligned for CP_WAIT(2)
        uint32_t aA = sb + (uint32_t)(s & 3) * STAGE;
        uint32_t bB = aA + 16384;
        #pragma unroll
        for (int ks = 0; ks < 4; ks++) {
            uint32_t af[4][4], bf[NJ][2];
            #pragma unroll
            for (int i = 0; i < 4; i++) {
                int row = wm * 64 + i * 16 + (lane & 15);
                int kb = ks * 32 + (lane >> 4) * 16;
                uint32_t sw = SMEM_SWIZZLE_128B((uint32_t)(row * 128 + kb));
                LDMATRIX_X4(af[i][0], af[i][1], af[i][2], af[i][3], aA + sw);
            }
            #pragma unroll
            for (int jp = 0; jp < NJ / 2; jp++) {
                int n = wn * (BN / 4) + jp * 16 + (lane >> 4) * 8 + (lane & 7);
                int kb = ks * 32 + ((lane >> 3) & 1) * 16;
                uint32_t sw = SMEM_SWIZZLE_128B((uint32_t)(n * 128 + kb));
                LDMATRIX_X4(bf[2*jp][0], bf[2*jp][1], bf[2*jp+1][0], bf[2*jp+1][1], bB + sw);
            }
            #pragma unroll
            for (int i = 0; i < 4; i++)
                #pragma unroll
                for (int j = 0; j < NJ; j++) mma16816h(acc[i][j], af[i], bf[j]);
        }
    }

    // ---- epilogue
    int gr = lane >> 2;        // 0..7
    int gc = (lane & 3) * 2;   // 0,2,4,6
    #pragma unroll
    for (int i = 0; i < 4; i++) {
        int row0 = blockIdx.y * 128 + wm * 64 + i * 16 + gr;
        #pragma unroll
        for (int j = 0; j < NJ; j++) {
            int col = blockIdx.x * BN + wn * (BN / 4) + j * 8 + gc;
            float2 bv = *(const float2*)(bias + col);
            #pragma unroll
            for (int half = 0; half < 2; half++) {
                int row = row0 + half * 8;
                size_t idx = (size_t)row * Dout + col;
                float2 o;
                o.x = acc[i][j][half * 2 + 0] + bv.x;
                o.y = acc[i][j][half * 2 + 1] + bv.y;
                if (EPI == 1) { o.x = gelu_f(o.x); o.y = gelu_f(o.y); }
                if (EPI == 2) {
                    float2 a1 = *(const float2*)(add1 + idx);
                    float2 a2 = *(const float2*)(add2 + idx);
                    o.x += a1.x + a2.x; o.y += a1.y + a2.y;
                }
                if (EPI == 3) {
                    float2 a1 = *(const float2*)(add1 + idx);
                    o.x += a1.x; o.y += a1.y;
                }
                if (WF32) *(float2*)(C + idx) = o;
                if (WPL)  *(__half2*)(PH + idx) = __floats2half2_rn(o.x, o.y);
            }
        }
    }
}

// ---------------- RMSNorm -> fp16 -----------------------------------------------
__global__ void rmsnorm_h(const float* __restrict__ x,
                          const float* __restrict__ w,
                          __half* __restrict__ H) {
    int row = blockIdx.x;
    int t = threadIdx.x;  // 256
    const float4* xr = (const float4*)(x + (size_t)row * MODEL_DIM);
    float4 v0 = xr[t];
    float4 v1 = xr[t + 256];
    float s = v0.x*v0.x + v0.y*v0.y + v0.z*v0.z + v0.w*v0.w
            + v1.x*v1.x + v1.y*v1.y + v1.z*v1.z + v1.w*v1.w;
    #pragma unroll
    for (int o = 16; o > 0; o >>= 1) s += __shfl_xor_sync(0xffffffffu, s, o);
    __shared__ float red[8];
    if ((t & 31) == 0) red[t >> 5] = s;
    __syncthreads();
    float tot = red[0]+red[1]+red[2]+red[3]+red[4]+red[5]+red[6]+red[7];
    float inv = 1.0f / (sqrtf(tot / (float)MODEL_DIM) + EPSV);
    const float4* wr = (const float4*)w;
    float4 w0 = wr[t], w1 = wr[t + 256];
    __half2* Hr = (__half2*)(H + (size_t)row * MODEL_DIM);
    Hr[t*2]       = __floats2half2_rn(w0.x*v0.x*inv, w0.y*v0.y*inv);
    Hr[t*2+1]     = __floats2half2_rn(w0.z*v0.z*inv, w0.w*v0.w*inv);
    Hr[512+t*2]   = __floats2half2_rn(w1.x*v1.x*inv, w1.y*v1.y*inv);
    Hr[512+t*2+1] = __floats2half2_rn(w1.z*v1.z*inv, w1.w*v1.w*inv);
}

// ---------------- gamma / h_t elementwise (+ ht fp16) ----------------------------
__global__ void gamma_ht_kernel(const float* __restrict__ t,
                                const float* __restrict__ m2,
                                const float* __restrict__ z,
                                const float* __restrict__ glin,
                                const float* __restrict__ x,
                                float* __restrict__ gamma,
                                float* __restrict__ ht,
                                __half* __restrict__ hth) {
    size_t i = (size_t)(blockIdx.x * blockDim.x + threadIdx.x);
    float4 tv = ((const float4*)t)[i];
    float4 mv = ((const float4*)m2)[i];
    float4 zv = ((const float4*)z)[i];
    float4 gv = ((const float4*)glin)[i];
    float4 xv = ((const float4*)x)[i];
    float4 gm, h;
    gm.x = sigmoid_f(tv.x + mv.x); gm.y = sigmoid_f(tv.y + mv.y);
    gm.z = sigmoid_f(tv.z + mv.z); gm.w = sigmoid_f(tv.w + mv.w);
    h.x = zv.x * sigmoid_f(gv.x) + gm.x * xv.x;
    h.y = zv.y * sigmoid_f(gv.y) + gm.y * xv.y;
    h.z = zv.z * sigmoid_f(gv.z) + gm.z * xv.z;
    h.w = zv.w * sigmoid_f(gv.w) + gm.w * xv.w;
    ((float4*)gamma)[i] = gm;
    ((float4*)ht)[i] = h;
    ((__half2*)hth)[i*2]   = __floats2half2_rn(h.x, h.y);
    ((__half2*)hth)[i*2+1] = __floats2half2_rn(h.z, h.w);
}

// ---------------- cumprod ---------------------------------------------------------
__global__ void cumprod_local(const float* __restrict__ gamma, float* __restrict__ outp) {
    int c = blockIdx.x, bh = blockIdx.y, d2 = threadIdx.x;
    size_t base = (size_t)bh * SEQ * DH + (size_t)c * CS * DH + d2;
    float p = 1.0f;
    for (int i = 0; i < CS; i++) {
        p *= gamma[base + (size_t)i * DH];
        outp[base + (size_t)i * DH] = p;
    }
    g_cp_tot[(bh * NCHUNK + c) * DH + d2] = p;
}
__global__ void cumprod_scan() {
    int lane = blockIdx.x * blockDim.x + threadIdx.x;
    int bh = lane / DH, d2 = lane % DH;
    float r = 1.0f;
    for (int c = 0; c < NCHUNK; c++) {
        int idx = (bh * NCHUNK + c) * DH + d2;
        g_cp_pref[idx] = r;
        r *= g_cp_tot[idx];
    }
}
__global__ void cumprod_apply(float* __restrict__ outp) {
    int c = blockIdx.x, bh = blockIdx.y, d2 = threadIdx.x;
    if (c == 0) return;
    float pref = g_cp_pref[(bh * NCHUNK + c) * DH + d2];
    size_t base = (size_t)bh * SEQ * DH + (size_t)c * CS * DH + d2;
    for (int i = 0; i < CS; i++) outp[base + (size_t)i * DH] *= pref;
}

// ---------------- tensor-core attention over 64 memory tokens ---------------------
// per block: (b, h, 64-row s-tile). QK^T (fp16 mma) -> fp32 softmax -> PV (fp16 mma).
#define AQ_OFF 0u
#define AK_OFF 16384u
#define AV_OFF 32768u
#define ASC_OFF 49152u
#define APS_OFF (49152u + 64u*68u*4u)
#define ATTN_SMEM2 (49152 + 64*68*4 + 8192)
__global__ void __launch_bounds__(128, 1)
attn_mma(const __half* __restrict__ qah,
         const __half* __restrict__ kvh,
         __half* __restrict__ ctxh) {
    extern __shared__ __align__(1024) char smc[];
    uint32_t sb = smem_to_u32(smc);
    float* sc = (float*)(smc + ASC_OFF);
    int stile = blockIdx.x, h = blockIdx.y, b = blockIdx.z;
    int s0 = stile * 64;
    int tid = threadIdx.x, lane = tid & 31, wid = tid >> 5;
    int wm = wid & 1, wn = wid >> 1;   // 2 (M) x 2 (N)

    // Q/K: 64 rows x 256B each, split into 2 chunks of 128B rows (SW128)
    #pragma unroll
    for (int i = 0; i < 8; i++) {
        int idx = tid + i * 128;       // 0..1023
        int r = idx >> 4, u = idx & 15;
        int c = u >> 3, uc = u & 7;
        uint32_t sw = SMEM_SWIZZLE_128B((uint32_t)(r * 128 + uc * 16));
        CP_ASYNC_16(sb + AQ_OFF + c * 8192 + sw,
                    qah + (size_t)(b * SEQ + s0 + r) * MODEL_DIM + h * 128 + u * 8);
        CP_ASYNC_16(sb + AK_OFF + c * 8192 + sw,
                    kvh + (size_t)(b * MEM_TOKENS + r) * (2 * MODEL_DIM) + h * 128 + u * 8);
    }
    CP_COMMIT();
    // V transposed: Vt[d][m] (128 rows x 64 halves = 128B rows, SW128)
    for (int idx = tid; idx < 8192; idx += 128) {
        int m = idx >> 7, d = idx & 127;
        __half v = kvh[(size_t)(b * MEM_TOKENS + m) * (2 * MODEL_DIM) + MODEL_DIM + h * 128 + d];
        *(__half*)(smc + AV_OFF + SMEM_SWIZZLE_128B((uint32_t)(d * 128 + m * 2))) = v;
    }
    CP_WAIT(0);
    __syncthreads();

    // ---- S = Q K^T  (M=64, N=64, K=128 in 2 chunks of 64)
    float acc[2][4][4];
    #pragma unroll
    for (int i = 0; i < 2; i++)
        #pragma unroll
        for (int j = 0; j < 4; j++)
            #pragma unroll
            for (int q = 0; q < 4; q++) acc[i][j][q] = 0.0f;
    #pragma unroll
    for (int c = 0; c < 2; c++) {
        uint32_t qA = sb + AQ_OFF + c * 8192;
        uint32_t kB = sb + AK_OFF + c * 8192;
        #pragma unroll
        for (int ks = 0; ks < 4; ks++) {
            uint32_t af[2][4], bf[4][2];
            #pragma unroll
            for (int i = 0; i < 2; i++) {
                int row = wm * 32 + i * 16 + (lane & 15);
                int kb = ks * 32 + (lane >> 4) * 16;
                LDMATRIX_X4(af[i][0], af[i][1], af[i][2], af[i][3],
                            qA + SMEM_SWIZZLE_128B((uint32_t)(row * 128 + kb)));
            }
            #pragma unroll
            for (int jp = 0; jp < 2; jp++) {
                int n = wn * 32 + jp * 16 + (lane >> 4) * 8 + (lane & 7);
                int kb = ks * 32 + ((lane >> 3) & 1) * 16;
                LDMATRIX_X4(bf[2*jp][0], bf[2*jp][1], bf[2*jp+1][0], bf[2*jp+1][1],
                            kB + SMEM_SWIZZLE_128B((uint32_t)(n * 128 + kb)));
            }
            #pragma unroll
            for (int i = 0; i < 2; i++)
                #pragma unroll
                for (int j = 0; j < 4; j++) mma16816h(acc[i][j], af[i], bf[j]);
        }
    }
    const float scale = 0.08838834764831845f;  // 1/sqrt(128)
    int gr = lane >> 2, gc = (lane & 3) * 2;
    #pragma unroll
    for (int i = 0; i < 2; i++)
        #pragma unroll
        for (int j = 0; j < 4; j++)
            #pragma unroll
            for (int half = 0; half < 2; half++) {
                int row = wm * 32 + i * 16 + gr + half * 8;
                int col = wn * 32 + j * 8 + gc;
                sc[row * 68 + col]     = acc[i][j][half * 2 + 0] * scale;
                sc[row * 68 + col + 1] = acc[i][j][half * 2 + 1] * scale;
            }
    __syncthreads();

    // ---- softmax (fp32), P -> fp16 smem
    if (tid < 64) {
        float* row = &sc[tid * 68];
        float mx = -1e30f;
        for (int m = 0; m < 64; m++) mx = fmaxf(mx, row[m]);
        float s = 0.0f;
        for (int m = 0; m < 64; m++) { float e = expf(row[m] - mx); row[m] = e; s += e; }
        float inv = 1.0f / s;
        for (int m = 0; m < 64; m++)
            *(__half*)(smc + APS_OFF + SMEM_SWIZZLE_128B((uint32_t)(tid * 128 + m * 2))) =
                __float2half_rn(row[m] * inv);
    }
    __syncthreads();

    // ---- ctx = P V  (M=64, N=128(dh), K=64(mem))  W = Vt[128][64]
    float acc2[2][8][4];
    #pragma unroll
    for (int i = 0; i < 2; i++)
        #pragma unroll
        for (int j = 0; j < 8; j++)
            #pragma unroll
            for (int q = 0; q < 4; q++) acc2[i][j][q] = 0.0f;
    #pragma unroll
    for (int ks = 0; ks < 4; ks++) {
        uint32_t af[2][4], bf[8][2];
        #pragma unroll
        for (int i = 0; i < 2; i++) {
            int row = wm * 32 + i * 16 + (lane & 15);
            int kb = ks * 32 + (lane >> 4) * 16;
            LDMATRIX_X4(af[i][0], af[i][1], af[i][2], af[i][3],
                        sb + APS_OFF + SMEM_SWIZZLE_128B((uint32_t)(row * 128 + kb)));
        }
        #pragma unroll
        for (int jp = 0; jp < 4; jp++) {
            int n = wn * 64 + jp * 16 + (lane >> 4) * 8 + (lane & 7);
            int kb = ks * 32 + ((lane >> 3) & 1) * 16;
            LDMATRIX_X4(bf[2*jp][0], bf[2*jp][1], bf[2*jp+1][0], bf[2*jp+1][1],
                        sb + AV_OFF + SMEM_SWIZZLE_128B((uint32_t)(n * 128 + kb)));
        }
        #pragma unroll
        for (int i = 0; i < 2; i++)
            #pragma unroll
            for (int j = 0; j < 8; j++) mma16816h(acc2[i][j], af[i], bf[j]);
    }
    #pragma unroll
    for (int i = 0; i < 2; i++)
        #pragma unroll
        for (int j = 0; j < 8; j++)
            #pragma unroll
            for (int half = 0; half < 2; half++) {
                int row = wm * 32 + i * 16 + gr + half * 8;
                int d = wn * 64 + j * 8 + gc;
                size_t idx = (size_t)(b * SEQ + s0 + row) * MODEL_DIM + h * 128 + d;
                *(__half2*)(ctxh + idx) =
                    __floats2half2_rn(acc2[i][j][half * 2 + 0], acc2[i][j][half * 2 + 1]);
            }
}

// ---------------- host launcher -----------------------------------------------------
extern "C" void kernel_launch(void* const* d_in, const int* in_sizes, int n_in,
                              void* d_out, int out_size) {
    bool sig = (in_sizes[3] == MODEL_DIM);
    const float *x, *memory, *wk, *bk, *wz, *bz, *wg, *bg, *n1w, *n2w;
    const float *md1, *mb1, *md2, *mb2, *mcw, *mcb;
    const float *awq, *abq, *awk, *abk, *awv, *abv, *awo, *abo;
    const float *f1, *fb1, *f2, *fb2;
    #define IN(i) ((const float*)d_in[(i)])
    if (sig) {
        x = IN(0);  memory = IN(1);
        wk = IN(4);  bk = IN(5);  wz = IN(8);  bz = IN(9);  wg = IN(10); bg = IN(11);
        n1w = IN(12); n2w = IN(13);
        md1 = IN(14); mb1 = IN(15); md2 = IN(16); mb2 = IN(17); mcw = IN(18); mcb = IN(19);
        awq = IN(20); abq = IN(21); awk = IN(22); abk = IN(23); awv = IN(24); abv = IN(25);
        awo = IN(26); abo = IN(27);
        f1 = IN(28); fb1 = IN(29); f2 = IN(30); fb2 = IN(31);
    } else {
        x = IN(0);  memory = IN(1);
        wk = IN(3);  wz = IN(5);  wg = IN(6);
        md1 = IN(7); md2 = IN(8); mcw = IN(9);
        awq = IN(10); awk = IN(11); awv = IN(12); awo = IN(13);
        f1 = IN(14); f2 = IN(15);
        bk = IN(17); bz = IN(19); bg = IN(20);
        mb1 = IN(21); mb2 = IN(22); mcb = IN(23);
        abq = IN(24); abk = IN(25); abv = IN(26); abo = IN(27);
        fb1 = IN(28); fb2 = IN(29);
        n1w = IN(30); n2w = IN(31);
    }
    #undef IN

    float *zb, *glin, *tb, *m2b, *gammab, *htb, *xresb, *kvbias;
    cudaGetSymbolAddress((void**)&zb,    g_z);
    cudaGetSymbolAddress((void**)&glin,  g_glin);
    cudaGetSymbolAddress((void**)&tb,    g_t);
    cudaGetSymbolAddress((void**)&m2b,   g_m2);
    cudaGetSymbolAddress((void**)&gammab,g_gamma);
    cudaGetSymbolAddress((void**)&htb,   g_ht);
    cudaGetSymbolAddress((void**)&xresb, g_xres);
    cudaGetSymbolAddress((void**)&kvbias,g_kvbias);

    __half *xh,*xnh,*zh,*kh,*uh,*hth,*memh,*qah,*kvh,*ctxh,*xn2h,*a1h;
    cudaGetSymbolAddress((void**)&xh,  g_xh);
    cudaGetSymbolAddress((void**)&xnh, g_xnh);
    cudaGetSymbolAddress((void**)&zh,  g_zh);
    cudaGetSymbolAddress((void**)&kh,  g_kh);
    cudaGetSymbolAddress((void**)&uh,  g_uh);
    cudaGetSymbolAddress((void**)&hth, g_hth);
    cudaGetSymbolAddress((void**)&memh,g_memh);
    cudaGetSymbolAddress((void**)&qah, g_qah);
    cudaGetSymbolAddress((void**)&kvh, g_kvh);
    cudaGetSymbolAddress((void**)&ctxh,g_ctxh);
    cudaGetSymbolAddress((void**)&xn2h,g_xn2h);
    cudaGetSymbolAddress((void**)&a1h, g_a1h);

    __half *wkT,*wzT,*wgT,*mcwT,*awqT,*awoT,*awkvT,*md1T,*md2T,*f1T,*f2T;
    cudaGetSymbolAddress((void**)&wkT,  g_wk);
    cudaGetSymbolAddress((void**)&wzT,  g_wz);
    cudaGetSymbolAddress((void**)&wgT,  g_wg);
    cudaGetSymbolAddress((void**)&mcwT, g_mcw);
    cudaGetSymbolAddress((void**)&awqT, g_awq);
    cudaGetSymbolAddress((void**)&awoT, g_awo);
    cudaGetSymbolAddress((void**)&awkvT,g_awkv);
    cudaGetSymbolAddress((void**)&md1T, g_md1);
    cudaGetSymbolAddress((void**)&md2T, g_md2);
    cudaGetSymbolAddress((void**)&f1T,  g_f1);
    cudaGetSymbolAddress((void**)&f2T,  g_f2);

    float* out = (float*)d_out;
    float* cum = out + (size_t)NTOK * MODEL_DIM;

    const int SM256 = 16384 + 256 * 128;   // 49152/stage, 4 stages = 196608
    const int SM128 = 16384 + 128 * 128;   // 32768/stage, 4 stages = 131072
    cudaFuncSetAttribute((const void*)hgemm<256,0,false,true>,  cudaFuncAttributeMaxDynamicSharedMemorySize, 4*SM256);
    cudaFuncSetAttribute((const void*)hgemm<256,0,true,true>,   cudaFuncAttributeMaxDynamicSharedMemorySize, 4*SM256);
    cudaFuncSetAttribute((const void*)hgemm<256,0,true,false>,  cudaFuncAttributeMaxDynamicSharedMemorySize, 4*SM256);
    cudaFuncSetAttribute((const void*)hgemm<256,1,false,true>,  cudaFuncAttributeMaxDynamicSharedMemorySize, 4*SM256);
    cudaFuncSetAttribute((const void*)hgemm<256,2,true,false>,  cudaFuncAttributeMaxDynamicSharedMemorySize, 4*SM256);
    cudaFuncSetAttribute((const void*)hgemm<256,3,true,false>,  cudaFuncAttributeMaxDynamicSharedMemorySize, 4*SM256);
    cudaFuncSetAttribute((const void*)hgemm<128,1,false,true>,  cudaFuncAttributeMaxDynamicSharedMemorySize, 4*SM128);
    cudaFuncSetAttribute((const void*)hgemm<128,0,false,true>,  cudaFuncAttributeMaxDynamicSharedMemorySize, 4*SM128);
    cudaFuncSetAttribute(attn_mma, cudaFuncAttributeMaxDynamicSharedMemorySize, ATTN_SMEM2);

    // ---- weight transposes (fp16, coalesced half2 stores)
    dim3 tb8(32, 8);
    dim3 gT(MODEL_DIM / 32, MODEL_DIM / 64);
    transpose_h2<<<gT, tb8>>>(wk,  wkT,  MODEL_DIM, MODEL_DIM);
    transpose_h2<<<gT, tb8>>>(wz,  wzT,  MODEL_DIM, MODEL_DIM);
    transpose_h2<<<gT, tb8>>>(wg,  wgT,  MODEL_DIM, MODEL_DIM);
    transpose_h2<<<gT, tb8>>>(mcw, mcwT, MODEL_DIM, MODEL_DIM);
    transpose_h2<<<gT, tb8>>>(awq, awqT, MODEL_DIM, MODEL_DIM);
    transpose_h2<<<gT, tb8>>>(awo, awoT, MODEL_DIM, MODEL_DIM);
    transpose_h2<<<gT, tb8>>>(awk, awkvT,                               MODEL_DIM, MODEL_DIM);
    transpose_h2<<<gT, tb8>>>(awv, awkvT + (size_t)MODEL_DIM*MODEL_DIM, MODEL_DIM, MODEL_DIM);
    transpose_h2<<<dim3(INNER_DIM / 32, MODEL_DIM / 64), tb8>>>(md1, md1T, MODEL_DIM, INNER_DIM);
    transpose_h2<<<dim3(MODEL_DIM / 32, INNER_DIM / 64), tb8>>>(md2, md2T, INNER_DIM, MODEL_DIM);
    transpose_h2<<<dim3(FFN_DIM / 32,  MODEL_DIM / 64), tb8>>>(f1, f1T, MODEL_DIM, FFN_DIM);
    transpose_h2<<<dim3(MODEL_DIM / 32, FFN_DIM / 64),  tb8>>>(f2, f2T, FFN_DIM, MODEL_DIM);
    concat_bias<<<(2 * MODEL_DIM) / 256, 256>>>(abk, abv);

    // ---- fp16 copies of raw inputs
    cvt_h<<<(NTOK * MODEL_DIM / 4) / 256, 256>>>(x, xh);
    cvt_h<<<(BATCH * MEM_TOKENS * MODEL_DIM / 4) / 64, 64>>>(memory, memh);

    dim3 gDD(MODEL_DIM / 256, NTOK / 128);   // (8, 32)
    dim3 gDF(FFN_DIM / 256,  NTOK / 128);    // (32, 32)

    // 1) xn = rmsnorm(x, n1w) -> fp16
    rmsnorm_h<<<NTOK, 256>>>(x, n1w, xnh);
    // 2) projections
    hgemm<256,0,false,true><<<gDD, 256, 4*SM256>>>(xnh, wkT, bk, nullptr, kh, MODEL_DIM, MODEL_DIM, nullptr, nullptr);
    hgemm<256,0,true,true><<<gDD, 256, 4*SM256>>>(xnh, wzT, bz, zb, zh, MODEL_DIM, MODEL_DIM, nullptr, nullptr);
    hgemm<256,0,true,false><<<gDD, 256, 4*SM256>>>(xh, wgT, bg, glin, nullptr, MODEL_DIM, MODEL_DIM, nullptr, nullptr);
    // 3) decay net
    hgemm<128,1,false,true><<<dim3(INNER_DIM/128, NTOK/128), 256, 4*SM128>>>(zh, md1T, mb1, nullptr, uh, MODEL_DIM, INNER_DIM, nullptr, nullptr);
    hgemm<256,0,true,false><<<gDD, 256, 4*SM256>>>(uh, md2T, mb2, tb, nullptr, INNER_DIM, MODEL_DIM, nullptr, nullptr);
    hgemm<256,0,true,false><<<gDD, 256, 4*SM256>>>(kh, mcwT, mcb, m2b, nullptr, MODEL_DIM, MODEL_DIM, nullptr, nullptr);
    // 4) gamma + h_t (+ht fp16)
    gamma_ht_kernel<<<(NTOK * MODEL_DIM) / (256 * 4), 256>>>(tb, m2b, zb, glin, x, gammab, htb, hth);
    // 5) cumprod (second output)
    cumprod_local<<<dim3(NCHUNK, NBH), DH>>>(gammab, cum);
    cumprod_scan<<<(NBH * DH) / 256, 256>>>();
    cumprod_apply<<<dim3(NCHUNK, NBH), DH>>>(cum);
    // 6) attention (all-fp16 mma path)
    hgemm<256,0,false,true><<<gDD, 256, 4*SM256>>>(hth, awqT, abq, nullptr, qah, MODEL_DIM, MODEL_DIM, nullptr, nullptr);
    hgemm<128,0,false,true><<<dim3(2*MODEL_DIM/128, 1), 256, 4*SM128>>>(memh, awkvT, kvbias, nullptr, kvh, MODEL_DIM, 2*MODEL_DIM, nullptr, nullptr);
    attn_mma<<<dim3(SEQ / 64, NUM_HEADS, BATCH), 128, ATTN_SMEM2>>>(qah, kvh, ctxh);
    // 7) x_res = x + h_t + (ctx@awo + abo)
    hgemm<256,2,true,false><<<gDD, 256, 4*SM256>>>(ctxh, awoT, abo, xresb, nullptr, MODEL_DIM, MODEL_DIM, x, htb);
    // 8) FFN + residual -> first output
    rmsnorm_h<<<NTOK, 256>>>(xresb, n2w, xn2h);
    hgemm<256,1,false,true><<<gDF, 256, 4*SM256>>>(xn2h, f1T, fb1, nullptr, a1h, MODEL_DIM, FFN_DIM, nullptr, nullptr);
    hgemm<256,3,true,false><<<gDD, 256, 4*SM256>>>(a1h, f2T, fb2, out, nullptr, FFN_DIM, MODEL_DIM, xresb, nullptr);
}